// round 14
// baseline (speedup 1.0000x reference)
#include <cuda_runtime.h>
#include <cuda_fp16.h>
#include <cstdint>
#include <cstddef>

// Problem constants
#define BSZ   2
#define NSEQ  2048
#define CDIM  1024
#define HN    16
#define DH    64
#define QSCALE 0.125f
#define ATTN_BIAS_F (-7.625f)

#define NELEM_X   ((size_t)BSZ * NSEQ * CDIM)
#define NELEM_W   ((size_t)3 * CDIM * CDIM)
#define NELEM_WP  ((size_t)CDIM * CDIM)
#define NELEM_HD  ((size_t)BSZ * HN * NSEQ * DH)

__device__ __half g_xhi[NELEM_X],  g_xlo[NELEM_X];
__device__ __half g_whi[NELEM_W],  g_wlo[NELEM_W];
__device__ __half g_wphi[NELEM_WP], g_wplo[NELEM_WP];
__device__ __half g_qhi[NELEM_HD], g_qlo[NELEM_HD];
__device__ __half g_khi[NELEM_HD], g_klo[NELEM_HD];
__device__ __half g_vhi[NELEM_HD], g_vlo[NELEM_HD];
__device__ __half g_avhi[NELEM_X], g_avlo[NELEM_X];
__device__ float g_av[NELEM_X];

// ---------------------------------------------------------------------------
// Helpers
// ---------------------------------------------------------------------------
__device__ __forceinline__ uint32_t smem_u32(const void* p) {
    uint32_t a;
    asm("{ .reg .u64 t; cvta.to.shared.u64 t, %1; cvt.u32.u64 %0, t; }"
        : "=r"(a) : "l"(p));
    return a;
}

// fp32-accum fp16 MMA: main hi*hi term
__device__ __forceinline__ void mma_f32acc(float c[4], const uint32_t a[4],
                                           const uint32_t b[2]) {
    asm volatile(
        "mma.sync.aligned.m16n8k16.row.col.f32.f16.f16.f32 "
        "{%0,%1,%2,%3}, {%4,%5,%6,%7}, {%8,%9}, {%0,%1,%2,%3};\n"
        : "+f"(c[0]), "+f"(c[1]), "+f"(c[2]), "+f"(c[3])
        : "r"(a[0]), "r"(a[1]), "r"(a[2]), "r"(a[3]), "r"(b[0]), "r"(b[1]));
}
// f16-accum fp16 MMA: cross terms (~2^-11 of total magnitude)
__device__ __forceinline__ void mma_f16acc(uint32_t c[2], const uint32_t a[4],
                                           const uint32_t b[2]) {
    asm volatile(
        "mma.sync.aligned.m16n8k16.row.col.f16.f16.f16.f16 "
        "{%0,%1}, {%2,%3,%4,%5}, {%6,%7}, {%0,%1};\n"
        : "+r"(c[0]), "+r"(c[1])
        : "r"(a[0]), "r"(a[1]), "r"(a[2]), "r"(a[3]), "r"(b[0]), "r"(b[1]));
}
__device__ __forceinline__ void addcross(float c[4], const uint32_t ch[2]) {
    float2 v0 = __half22float2(*(const __half2*)&ch[0]);
    float2 v1 = __half22float2(*(const __half2*)&ch[1]);
    c[0] += v0.x; c[1] += v0.y; c[2] += v1.x; c[3] += v1.y;
}

// ldmatrix x4 (warp-collective)
__device__ __forceinline__ void ldsm_x4(uint32_t r[4], uint32_t addr) {
    asm volatile("ldmatrix.sync.aligned.m8n8.x4.shared.b16 {%0,%1,%2,%3}, [%4];"
                 : "=r"(r[0]), "=r"(r[1]), "=r"(r[2]), "=r"(r[3]) : "r"(addr));
}
// A-tile (16x16): matrices = (rows,k0),(rows+8,k0),(rows,k0+8),(rows+8,k0+8)
__device__ __forceinline__ uint32_t a_addr(uint32_t base, int row0, int k0,
                                           int SB, int lane) {
    int mat = lane >> 3, r = lane & 7;
    int row = row0 + r + ((mat & 1) << 3);
    int k   = k0 + ((mat >> 1) << 3);
    return base + row * SB + k * 2;
}
// B-pair (n-tiles n0, n0+8): regs[0,1] = frag n0, regs[2,3] = frag n0+8
__device__ __forceinline__ uint32_t b_addr(uint32_t base, int n0, int k0,
                                           int SB, int lane) {
    int mat = lane >> 3, r = lane & 7;
    int row = n0 + r + ((mat >> 1) << 3);
    int k   = k0 + ((mat & 1) << 3);
    return base + row * SB + k * 2;
}

__device__ __forceinline__ void splitf(float v, __half& h, __half& l) {
    h = __float2half_rn(v);
    l = __float2half_rn(v - __half2float(h));
}
__device__ __forceinline__ uint32_t h2u(__half a, __half b) {
    __half2 t = __halves2half2(a, b);
    return *reinterpret_cast<uint32_t*>(&t);
}
__device__ __forceinline__ void split4(float4 v, uint2& hi, uint2& lo) {
    __half h0, h1, h2, h3, l0, l1, l2, l3;
    splitf(v.x, h0, l0); splitf(v.y, h1, l1);
    splitf(v.z, h2, l2); splitf(v.w, h3, l3);
    hi.x = h2u(h0, h1); hi.y = h2u(h2, h3);
    lo.x = h2u(l0, l1); lo.y = h2u(l2, l3);
}

__device__ __forceinline__ void cp16(uint32_t dst, const void* src) {
    asm volatile("cp.async.cg.shared.global [%0], [%1], 16;" :: "r"(dst), "l"(src));
}
#define CP_COMMIT() asm volatile("cp.async.commit_group;" ::: "memory")
#define CP_WAIT(N)  asm volatile("cp.async.wait_group %0;" :: "n"(N) : "memory")

// ---------------------------------------------------------------------------
// Elementwise split converters
// ---------------------------------------------------------------------------
__global__ void convert_x(const float* __restrict__ src) {
    int i = blockIdx.x * blockDim.x + threadIdx.x;
    float4 v = ((const float4*)src)[i];
    uint2 hi, lo; split4(v, hi, lo);
    ((uint2*)g_xhi)[i] = hi;
    ((uint2*)g_xlo)[i] = lo;
}
__global__ void convert_w(const float* __restrict__ src) {
    int i = blockIdx.x * blockDim.x + threadIdx.x;
    float4 v = ((const float4*)src)[i];
    uint2 hi, lo; split4(v, hi, lo);
    ((uint2*)g_whi)[i] = hi;
    ((uint2*)g_wlo)[i] = lo;
}
__global__ void convert_wp(const float* __restrict__ src) {
    int i = blockIdx.x * blockDim.x + threadIdx.x;
    float4 v = ((const float4*)src)[i];
    uint2 hi, lo; split4(v, hi, lo);
    ((uint2*)g_wphi)[i] = hi;
    ((uint2*)g_wplo)[i] = lo;
}

// ---------------------------------------------------------------------------
// GEMM: 128(M) x 128(N) CTA tile, 512 threads, 16 warps (4x4 grid,
// warp tile M32xN32), K-chunk 64, cp.async double-buffered, 1 CTA/SM,
// single __syncthreads per chunk, ldmatrix fragment loads.
// Stage layout (bytes): Ahi 0 | Alo 18432 | Bhi 36864 | Blo 55296; 73728/stage
// ---------------------------------------------------------------------------
#define GS 72
#define SBY (GS * 2)
#define G_STAGE_B 73728
#define GEMM_SMEM (2 * G_STAGE_B)    // 147456 B, 1 CTA/SM

__device__ __forceinline__ void gemm_mainloop_step(
    uint32_t sA, float acc[2][4][4], int wm, int wn, int lane)
{
    uint32_t cch[2][4][2];
#pragma unroll
    for (int i = 0; i < 2; i++)
#pragma unroll
        for (int j = 0; j < 4; j++) { cch[i][j][0] = 0u; cch[i][j][1] = 0u; }

#pragma unroll
    for (int ks = 0; ks < 4; ks++) {
        const int k0 = ks * 16;
        uint32_t bh0[4], bh1[4], bl0[4], bl1[4];
        uint32_t ba0 = b_addr(sA + 36864, wn * 32,      k0, SBY, lane);
        uint32_t ba1 = b_addr(sA + 36864, wn * 32 + 16, k0, SBY, lane);
        ldsm_x4(bh0, ba0);
        ldsm_x4(bh1, ba1);
        ldsm_x4(bl0, ba0 + 18432);
        ldsm_x4(bl1, ba1 + 18432);
#pragma unroll
        for (int mt = 0; mt < 2; mt++) {
            uint32_t ah[4], al[4];
            uint32_t aa = a_addr(sA, wm * 32 + mt * 16, k0, SBY, lane);
            ldsm_x4(ah, aa);
            ldsm_x4(al, aa + 18432);
            mma_f32acc(acc[mt][0], ah, bh0 + 0);
            mma_f32acc(acc[mt][1], ah, bh0 + 2);
            mma_f32acc(acc[mt][2], ah, bh1 + 0);
            mma_f32acc(acc[mt][3], ah, bh1 + 2);
            mma_f16acc(cch[mt][0], ah, bl0 + 0);
            mma_f16acc(cch[mt][1], ah, bl0 + 2);
            mma_f16acc(cch[mt][2], ah, bl1 + 0);
            mma_f16acc(cch[mt][3], ah, bl1 + 2);
            mma_f16acc(cch[mt][0], al, bh0 + 0);
            mma_f16acc(cch[mt][1], al, bh0 + 2);
            mma_f16acc(cch[mt][2], al, bh1 + 0);
            mma_f16acc(cch[mt][3], al, bh1 + 2);
        }
    }
#pragma unroll
    for (int i = 0; i < 2; i++)
#pragma unroll
        for (int j = 0; j < 4; j++) addcross(acc[i][j], cch[i][j]);
}

// ---------------------------------------------------------------------------
// QKV GEMM: x[4096,1024] @ wqkv[3072,1024]^T
// ---------------------------------------------------------------------------
__global__ void __launch_bounds__(512, 1)
tc_gemm_qkv()
{
    extern __shared__ __half smg[];
    const uint32_t sbase = smem_u32(smg);
    const int tid = threadIdx.x;
    const int wid = tid >> 5, lane = tid & 31;
    const int grp = lane >> 2, qd = lane & 3;
    const int wm = wid >> 2, wn = wid & 3;
    const int row0 = blockIdx.y * 128, col0 = blockIdx.x * 128;

    auto stage_load = [&](int s, int kb) {
        uint32_t so = sbase + (uint32_t)(s * G_STAGE_B);
#pragma unroll
        for (int it = 0; it < 2; it++) {     // A: 128 rows x 64 halves
            int f = tid + 512 * it;
            int row = f >> 3, q = f & 7;
            size_t asrc = (size_t)(row0 + row) * CDIM + kb * 64 + q * 8;
            uint32_t off = so + (uint32_t)(row * GS + q * 8) * 2;
            cp16(off,         g_xhi + asrc);
            cp16(off + 18432, g_xlo + asrc);
        }
#pragma unroll
        for (int it = 0; it < 2; it++) {     // B: 128 rows x 64 halves
            int f = tid + 512 * it;
            int row = f >> 3, q = f & 7;
            size_t bsrc = (size_t)(col0 + row) * CDIM + kb * 64 + q * 8;
            uint32_t off = so + 36864 + (uint32_t)(row * GS + q * 8) * 2;
            cp16(off,         g_whi + bsrc);
            cp16(off + 18432, g_wlo + bsrc);
        }
    };

    float acc[2][4][4];
#pragma unroll
    for (int i = 0; i < 2; i++)
#pragma unroll
        for (int j = 0; j < 4; j++)
#pragma unroll
            for (int t = 0; t < 4; t++) acc[i][j][t] = 0.f;

    stage_load(0, 0); CP_COMMIT();

    for (int kb = 0; kb < 16; kb++) {
        CP_WAIT(0);
        __syncthreads();
        if (kb < 15) { stage_load((kb + 1) & 1, kb + 1); CP_COMMIT(); }
        gemm_mainloop_step(sbase + (uint32_t)((kb & 1) * G_STAGE_B),
                           acc, wm, wn, lane);
    }

    // epilogue: scatter split outputs
#pragma unroll
    for (int mt = 0; mt < 2; mt++) {
        int r = row0 + wm * 32 + mt * 16 + grp;
        int b0 = r >> 11, n0 = r & 2047;
#pragma unroll
        for (int nt = 0; nt < 4; nt++) {
            int c3 = col0 + wn * 32 + nt * 8 + qd * 2;
            int which = c3 >> 10;
            int cc = c3 & 1023;
            int hh = cc >> 6;
            int d = cc & 63;
            float mul = (which == 0) ? QSCALE : 1.0f;
            float* a4 = acc[mt][nt];
            float v0 = a4[0] * mul, v1 = a4[1] * mul;
            float v2 = a4[2] * mul, v3 = a4[3] * mul;
            __half h0, h1, h2, h3, l0, l1, l2, l3;
            splitf(v0, h0, l0); splitf(v1, h1, l1);
            splitf(v2, h2, l2); splitf(v3, h3, l3);
            size_t head = ((size_t)b0 * HN + hh) * (size_t)NSEQ * DH;
            if (which < 2) {
                __half* dhi = which ? g_khi : g_qhi;
                __half* dlo = which ? g_klo : g_qlo;
                size_t idx = head + (size_t)n0 * DH + d;
                *(uint32_t*)(dhi + idx) = h2u(h0, h1);
                *(uint32_t*)(dlo + idx) = h2u(l0, l1);
                *(uint32_t*)(dhi + idx + 8 * DH) = h2u(h2, h3);
                *(uint32_t*)(dlo + idx + 8 * DH) = h2u(l2, l3);
            } else {
                size_t idx = head + (size_t)d * NSEQ + n0;
                g_vhi[idx] = h0;            g_vlo[idx] = l0;
                g_vhi[idx + NSEQ] = h1;     g_vlo[idx + NSEQ] = l1;
                g_vhi[idx + 8] = h2;        g_vlo[idx + 8] = l2;
                g_vhi[idx + NSEQ + 8] = h3; g_vlo[idx + NSEQ + 8] = l3;
            }
        }
    }
}

// ---------------------------------------------------------------------------
// Output projection GEMM: av[4096,1024] @ wproj[1024,1024]^T (pure fp16 in)
// ---------------------------------------------------------------------------
__global__ void __launch_bounds__(512, 1)
tc_gemm_proj(float* __restrict__ Cout)
{
    extern __shared__ __half smg[];
    const uint32_t sbase = smem_u32(smg);
    const int tid = threadIdx.x;
    const int wid = tid >> 5, lane = tid & 31;
    const int grp = lane >> 2, qd = lane & 3;
    const int wm = wid >> 2, wn = wid & 3;
    const int row0 = blockIdx.y * 128, col0 = blockIdx.x * 128;

    auto stage_load = [&](int s, int kb) {
        uint32_t so = sbase + (uint32_t)(s * G_STAGE_B);
#pragma unroll
        for (int it = 0; it < 2; it++) {
            int f = tid + 512 * it;
            int row = f >> 3, q = f & 7;
            size_t asrc = (size_t)(row0 + row) * CDIM + kb * 64 + q * 8;
            uint32_t off = so + (uint32_t)(row * GS + q * 8) * 2;
            cp16(off,         g_avhi + asrc);
            cp16(off + 18432, g_avlo + asrc);
        }
#pragma unroll
        for (int it = 0; it < 2; it++) {
            int f = tid + 512 * it;
            int row = f >> 3, q = f & 7;
            size_t bsrc = (size_t)(col0 + row) * CDIM + kb * 64 + q * 8;
            uint32_t off = so + 36864 + (uint32_t)(row * GS + q * 8) * 2;
            cp16(off,         g_wphi + bsrc);
            cp16(off + 18432, g_wplo + bsrc);
        }
    };

    float acc[2][4][4];
#pragma unroll
    for (int i = 0; i < 2; i++)
#pragma unroll
        for (int j = 0; j < 4; j++)
#pragma unroll
            for (int t = 0; t < 4; t++) acc[i][j][t] = 0.f;

    stage_load(0, 0); CP_COMMIT();

    for (int kb = 0; kb < 16; kb++) {
        CP_WAIT(0);
        __syncthreads();
        if (kb < 15) { stage_load((kb + 1) & 1, kb + 1); CP_COMMIT(); }
        gemm_mainloop_step(sbase + (uint32_t)((kb & 1) * G_STAGE_B),
                           acc, wm, wn, lane);
    }

#pragma unroll
    for (int mt = 0; mt < 2; mt++) {
        int r = row0 + wm * 32 + mt * 16 + grp;
#pragma unroll
        for (int nt = 0; nt < 4; nt++) {
            int cl = col0 + wn * 32 + nt * 8 + qd * 2;
            float* a4 = acc[mt][nt];
            float2 v0 = {a4[0], a4[1]};
            float2 v1 = {a4[2], a4[3]};
            *(float2*)(Cout + (size_t)r * CDIM + cl) = v0;
            *(float2*)(Cout + (size_t)(r + 8) * CDIM + cl) = v1;
        }
    }
}

// ---------------------------------------------------------------------------
// Fused sigmoid attention: 128 q-rows per CTA, 64-key tiles, 2 CTAs/SM,
// single __syncthreads per tile.
// smem (elems): Qhi 0 | Qlo 9216 | K stages @18432 (stride 9216, lo +4608)
//               | V stages @36864 (stride 9216, lo +4608). Total 55296.
// ---------------------------------------------------------------------------
#define AK_BASE 18432
#define AV_BASE 36864
#define ATTN_SMEM (55296 * 2)    // 110592 B

__global__ void __launch_bounds__(256, 2)
attn_kernel2(float* __restrict__ attn_out, float* __restrict__ av_out)
{
    extern __shared__ __half sma[];
    const uint32_t sbase = smem_u32(sma);
    const int tid = threadIdx.x;
    const int wid = tid >> 5, lane = tid & 31;
    const int grp = lane >> 2, qd = lane & 3;
    const int row0 = blockIdx.x * 128;
    const int bhid = blockIdx.y;
    const int b = bhid >> 4, h = bhid & 15;
    const size_t head = ((size_t)b * HN + h) * (size_t)NSEQ * DH;

    auto load_kv = [&](int jt_, int s) {
        uint32_t ko = sbase + (uint32_t)(AK_BASE + s * 9216) * 2;
        uint32_t vo = sbase + (uint32_t)(AV_BASE + s * 9216) * 2;
#pragma unroll
        for (int it = 0; it < 2; it++) {
            int f = tid + 256 * it;
            int row = f >> 3, q = f & 7;
            {
                size_t src = head + (size_t)(jt_ * 64 + row) * DH + q * 8;
                uint32_t off = ko + (uint32_t)(row * GS + q * 8) * 2;
                cp16(off,            g_khi + src);
                cp16(off + 4608 * 2, g_klo + src);
            }
            {
                size_t src = head + (size_t)row * NSEQ + (size_t)jt_ * 64 + q * 8;
                uint32_t off = vo + (uint32_t)(row * GS + q * 8) * 2;
                cp16(off,            g_vhi + src);
                cp16(off + 4608 * 2, g_vlo + src);
            }
        }
    };

    // prologue: Q (128x64) + tile 0
#pragma unroll
    for (int it = 0; it < 4; it++) {
        int f = tid + 256 * it;
        int row = f >> 3, q = f & 7;
        size_t src = head + (size_t)(row0 + row) * DH + q * 8;
        uint32_t off = sbase + (uint32_t)(row * GS + q * 8) * 2;
        cp16(off,            g_qhi + src);
        cp16(off + 9216 * 2, g_qlo + src);
    }
    load_kv(0, 0);
    CP_COMMIT();

    float oacc[8][4];
#pragma unroll
    for (int i = 0; i < 8; i++)
#pragma unroll
        for (int t = 0; t < 4; t++) oacc[i][t] = 0.f;

    for (int jt = 0; jt < NSEQ / 64; jt++) {
        CP_WAIT(0);
        __syncthreads();
        if (jt < NSEQ / 64 - 1) { load_kv(jt + 1, (jt + 1) & 1); CP_COMMIT(); }

        const uint32_t kb = sbase + (uint32_t)(AK_BASE + (jt & 1) * 9216) * 2;
        const uint32_t vb = sbase + (uint32_t)(AV_BASE + (jt & 1) * 9216) * 2;

        // ---- S = Q K^T : 8 n-tiles of 8 keys ----
        float sacc[8][4];
        uint32_t sch[8][2];
#pragma unroll
        for (int i = 0; i < 8; i++) {
#pragma unroll
            for (int t = 0; t < 4; t++) sacc[i][t] = 0.f;
            sch[i][0] = 0u; sch[i][1] = 0u;
        }

#pragma unroll
        for (int ks = 0; ks < 4; ks++) {
            const int k0 = ks * 16;
            uint32_t qfh[4], qfl[4];
            uint32_t qaddr = a_addr(sbase, wid * 16, k0, SBY, lane);
            ldsm_x4(qfh, qaddr);
            ldsm_x4(qfl, qaddr + 18432);
#pragma unroll
            for (int t = 0; t < 4; t++) {
                uint32_t kh4[4], kl4[4];
                uint32_t kaddr = b_addr(kb, t * 16, k0, SBY, lane);
                ldsm_x4(kh4, kaddr);
                ldsm_x4(kl4, kaddr + 9216);
                mma_f32acc(sacc[2 * t],     qfh, kh4 + 0);
                mma_f32acc(sacc[2 * t + 1], qfh, kh4 + 2);
                mma_f16acc(sch[2 * t],      qfh, kl4 + 0);
                mma_f16acc(sch[2 * t + 1],  qfh, kl4 + 2);
                mma_f16acc(sch[2 * t],      qfl, kh4 + 0);
                mma_f16acc(sch[2 * t + 1],  qfl, kh4 + 2);
            }
        }
#pragma unroll
        for (int i = 0; i < 8; i++) addcross(sacc[i], sch[i]);

        // ---- sigmoid + attn store + register P -> PV ----
        float* ab = attn_out
            ? attn_out + ((size_t)bhid * NSEQ + row0 + wid * 16 + grp) * NSEQ
                       + (size_t)jt * 64
            : nullptr;

        uint32_t och[8][2];
#pragma unroll
        for (int i = 0; i < 8; i++) { och[i][0] = 0u; och[i][1] = 0u; }

#pragma unroll
        for (int kc = 0; kc < 4; kc++) {
            float* c0 = sacc[2 * kc];
            float* c1 = sacc[2 * kc + 1];
            float p0 = __fdividef(1.f, 1.f + __expf(-(c0[0] + ATTN_BIAS_F)));
            float p1 = __fdividef(1.f, 1.f + __expf(-(c0[1] + ATTN_BIAS_F)));
            float p2 = __fdividef(1.f, 1.f + __expf(-(c0[2] + ATTN_BIAS_F)));
            float p3 = __fdividef(1.f, 1.f + __expf(-(c0[3] + ATTN_BIAS_F)));
            float p4 = __fdividef(1.f, 1.f + __expf(-(c1[0] + ATTN_BIAS_F)));
            float p5 = __fdividef(1.f, 1.f + __expf(-(c1[1] + ATTN_BIAS_F)));
            float p6 = __fdividef(1.f, 1.f + __expf(-(c1[2] + ATTN_BIAS_F)));
            float p7 = __fdividef(1.f, 1.f + __expf(-(c1[3] + ATTN_BIAS_F)));
            if (ab) {
                float2 w0 = {p0, p1}, w1 = {p2, p3}, w2 = {p4, p5}, w3 = {p6, p7};
                *(float2*)(ab + kc * 16 + 2 * qd) = w0;
                *(float2*)(ab + 8 * NSEQ + kc * 16 + 2 * qd) = w1;
                *(float2*)(ab + kc * 16 + 8 + 2 * qd) = w2;
                *(float2*)(ab + 8 * NSEQ + kc * 16 + 8 + 2 * qd) = w3;
            }
            __half h0, h1, h2, h3, h4, h5, h6, h7;
            __half l0, l1, l2, l3, l4, l5, l6, l7;
            splitf(p0, h0, l0); splitf(p1, h1, l1); splitf(p2, h2, l2); splitf(p3, h3, l3);
            splitf(p4, h4, l4); splitf(p5, h5, l5); splitf(p6, h6, l6); splitf(p7, h7, l7);
            uint32_t pah[4] = { h2u(h0, h1), h2u(h2, h3), h2u(h4, h5), h2u(h6, h7) };
            uint32_t pal[4] = { h2u(l0, l1), h2u(l2, l3), h2u(l4, l5), h2u(l6, l7) };
#pragma unroll
            for (int t = 0; t < 4; t++) {
                uint32_t vh4[4], vl4[4];
                uint32_t vaddr = b_addr(vb, t * 16, kc * 16, SBY, lane);
                ldsm_x4(vh4, vaddr);
                ldsm_x4(vl4, vaddr + 9216);
                mma_f32acc(oacc[2 * t],     pah, vh4 + 0);
                mma_f32acc(oacc[2 * t + 1], pah, vh4 + 2);
                mma_f16acc(och[2 * t],      pah, vl4 + 0);
                mma_f16acc(och[2 * t + 1],  pah, vl4 + 2);
                mma_f16acc(och[2 * t],      pal, vh4 + 0);
                mma_f16acc(och[2 * t + 1],  pal, vh4 + 2);
            }
        }
#pragma unroll
        for (int i = 0; i < 8; i++) addcross(oacc[i], och[i]);
    }

    // ---- epilogue: O -> fp32 av_out + split fp16 g_avhi/g_avlo ----
    const int r = row0 + wid * 16 + grp;
#pragma unroll
    for (int dt = 0; dt < 8; dt++) {
        int d = dt * 8 + qd * 2;
        size_t base = (((size_t)b * NSEQ + r) * HN + h) * DH + d;
        float2 v0 = {oacc[dt][0], oacc[dt][1]};
        float2 v1 = {oacc[dt][2], oacc[dt][3]};
        *(float2*)(av_out + base) = v0;
        *(float2*)(av_out + base + 8 * (size_t)CDIM) = v1;
        __half h0, h1, h2, h3, l0, l1, l2, l3;
        splitf(v0.x, h0, l0); splitf(v0.y, h1, l1);
        splitf(v1.x, h2, l2); splitf(v1.y, h3, l3);
        *(uint32_t*)(g_avhi + base) = h2u(h0, h1);
        *(uint32_t*)(g_avlo + base) = h2u(l0, l1);
        *(uint32_t*)(g_avhi + base + 8 * (size_t)CDIM) = h2u(h2, h3);
        *(uint32_t*)(g_avlo + base + 8 * (size_t)CDIM) = h2u(l2, l3);
    }
}

// ---------------------------------------------------------------------------
// Launch
// ---------------------------------------------------------------------------
extern "C" void kernel_launch(void* const* d_in, const int* in_sizes, int n_in,
                              void* d_out, int out_size)
{
    const float* x     = (const float*)d_in[0];
    const float* wqkv  = (const float*)d_in[1];
    const float* wproj = (const float*)d_in[2];
    float* out = (float*)d_out;

    const size_t SZ_ATTN = (size_t)BSZ * HN * NSEQ * NSEQ;
    const size_t SZ_AV   = (size_t)BSZ * NSEQ * CDIM;
    const bool full = ((size_t)out_size >= SZ_ATTN + 2 * SZ_AV);

    static float* g_av_dev = nullptr;
    static bool attr_done = false;
    if (!attr_done) {
        cudaFuncSetAttribute(tc_gemm_qkv,
                             cudaFuncAttributeMaxDynamicSharedMemorySize, GEMM_SMEM);
        cudaFuncSetAttribute(attn_kernel2,
                             cudaFuncAttributeMaxDynamicSharedMemorySize, ATTN_SMEM);
        cudaFuncSetAttribute(tc_gemm_proj,
                             cudaFuncAttributeMaxDynamicSharedMemorySize, GEMM_SMEM);
        cudaGetSymbolAddress((void**)&g_av_dev, g_av);
        attr_done = true;
    }

    // 0) split-convert inputs
    convert_x<<<(int)(NELEM_X / 4 / 256), 256>>>(x);
    convert_w<<<(int)(NELEM_W / 4 / 256), 256>>>(wqkv);
    convert_wp<<<(int)(NELEM_WP / 4 / 256), 256>>>(wproj);

    // 1) QKV projection -> split q/k (row-major) + v (transposed)
    tc_gemm_qkv<<<dim3(3 * CDIM / 128, (BSZ * NSEQ) / 128), 512, GEMM_SMEM>>>();

    // 2) Fused sigmoid attention
    float* attn_dst = full ? out : nullptr;
    float* av_dst   = full ? out + SZ_ATTN : g_av_dev;
    attn_kernel2<<<dim3(NSEQ / 128, BSZ * HN), 256, ATTN_SMEM>>>(attn_dst, av_dst);

    // 3) Output projection
    float* proj_dst = full ? out + SZ_ATTN + SZ_AV : out;
    tc_gemm_proj<<<dim3(CDIM / 128, (BSZ * NSEQ) / 128), 512, GEMM_SMEM>>>(proj_dst);
}

// round 15
// speedup vs baseline: 1.2874x; 1.2874x over previous
#include <cuda_runtime.h>
#include <cuda_fp16.h>
#include <cstdint>
#include <cstddef>

// Problem constants
#define BSZ   2
#define NSEQ  2048
#define CDIM  1024
#define HN    16
#define DH    64
#define QSCALE 0.125f
#define ATTN_BIAS_F (-7.625f)

#define NELEM_X   ((size_t)BSZ * NSEQ * CDIM)
#define NELEM_W   ((size_t)3 * CDIM * CDIM)
#define NELEM_WP  ((size_t)CDIM * CDIM)
#define NELEM_HD  ((size_t)BSZ * HN * NSEQ * DH)

__device__ __half g_xhi[NELEM_X],  g_xlo[NELEM_X];
__device__ __half g_whi[NELEM_W],  g_wlo[NELEM_W];
__device__ __half g_wphi[NELEM_WP], g_wplo[NELEM_WP];
__device__ __half g_qhi[NELEM_HD];                    // q: plain fp16 (scaled)
__device__ __half g_khi[NELEM_HD], g_klo[NELEM_HD];   // k: split
__device__ __half g_vhi[NELEM_HD];                    // v^T: plain fp16
__device__ __half g_avhi[NELEM_X];                    // av: plain fp16
__device__ float g_av[NELEM_X];

// ---------------------------------------------------------------------------
// Helpers
// ---------------------------------------------------------------------------
__device__ __forceinline__ uint32_t smem_u32(const void* p) {
    uint32_t a;
    asm("{ .reg .u64 t; cvta.to.shared.u64 t, %1; cvt.u32.u64 %0, t; }"
        : "=r"(a) : "l"(p));
    return a;
}

__device__ __forceinline__ void mma_f32acc(float c[4], const uint32_t a[4],
                                           const uint32_t b[2]) {
    asm volatile(
        "mma.sync.aligned.m16n8k16.row.col.f32.f16.f16.f32 "
        "{%0,%1,%2,%3}, {%4,%5,%6,%7}, {%8,%9}, {%0,%1,%2,%3};\n"
        : "+f"(c[0]), "+f"(c[1]), "+f"(c[2]), "+f"(c[3])
        : "r"(a[0]), "r"(a[1]), "r"(a[2]), "r"(a[3]), "r"(b[0]), "r"(b[1]));
}
__device__ __forceinline__ void mma_f16acc(uint32_t c[2], const uint32_t a[4],
                                           const uint32_t b[2]) {
    asm volatile(
        "mma.sync.aligned.m16n8k16.row.col.f16.f16.f16.f16 "
        "{%0,%1}, {%2,%3,%4,%5}, {%6,%7}, {%0,%1};\n"
        : "+r"(c[0]), "+r"(c[1])
        : "r"(a[0]), "r"(a[1]), "r"(a[2]), "r"(a[3]), "r"(b[0]), "r"(b[1]));
}
__device__ __forceinline__ void addcross(float c[4], const uint32_t ch[2]) {
    float2 v0 = __half22float2(*(const __half2*)&ch[0]);
    float2 v1 = __half22float2(*(const __half2*)&ch[1]);
    c[0] += v0.x; c[1] += v0.y; c[2] += v1.x; c[3] += v1.y;
}

__device__ __forceinline__ void ldsm_x4(uint32_t r[4], uint32_t addr) {
    asm volatile("ldmatrix.sync.aligned.m8n8.x4.shared.b16 {%0,%1,%2,%3}, [%4];"
                 : "=r"(r[0]), "=r"(r[1]), "=r"(r[2]), "=r"(r[3]) : "r"(addr));
}
__device__ __forceinline__ uint32_t a_addr(uint32_t base, int row0, int k0,
                                           int SB, int lane) {
    int mat = lane >> 3, r = lane & 7;
    int row = row0 + r + ((mat & 1) << 3);
    int k   = k0 + ((mat >> 1) << 3);
    return base + row * SB + k * 2;
}
__device__ __forceinline__ uint32_t b_addr(uint32_t base, int n0, int k0,
                                           int SB, int lane) {
    int mat = lane >> 3, r = lane & 7;
    int row = n0 + r + ((mat >> 1) << 3);
    int k   = k0 + ((mat & 1) << 3);
    return base + row * SB + k * 2;
}

__device__ __forceinline__ void splitf(float v, __half& h, __half& l) {
    h = __float2half_rn(v);
    l = __float2half_rn(v - __half2float(h));
}
__device__ __forceinline__ uint32_t h2u(__half a, __half b) {
    __half2 t = __halves2half2(a, b);
    return *reinterpret_cast<uint32_t*>(&t);
}
__device__ __forceinline__ void split4(float4 v, uint2& hi, uint2& lo) {
    __half h0, h1, h2, h3, l0, l1, l2, l3;
    splitf(v.x, h0, l0); splitf(v.y, h1, l1);
    splitf(v.z, h2, l2); splitf(v.w, h3, l3);
    hi.x = h2u(h0, h1); hi.y = h2u(h2, h3);
    lo.x = h2u(l0, l1); lo.y = h2u(l2, l3);
}

__device__ __forceinline__ void cp16(uint32_t dst, const void* src) {
    asm volatile("cp.async.cg.shared.global [%0], [%1], 16;" :: "r"(dst), "l"(src));
}
#define CP_COMMIT() asm volatile("cp.async.commit_group;" ::: "memory")
#define CP_WAIT(N)  asm volatile("cp.async.wait_group %0;" :: "n"(N) : "memory")

// ---------------------------------------------------------------------------
// Elementwise split converters
// ---------------------------------------------------------------------------
__global__ void convert_x(const float* __restrict__ src) {
    int i = blockIdx.x * blockDim.x + threadIdx.x;
    float4 v = ((const float4*)src)[i];
    uint2 hi, lo; split4(v, hi, lo);
    ((uint2*)g_xhi)[i] = hi;
    ((uint2*)g_xlo)[i] = lo;
}
__global__ void convert_w(const float* __restrict__ src) {
    int i = blockIdx.x * blockDim.x + threadIdx.x;
    float4 v = ((const float4*)src)[i];
    uint2 hi, lo; split4(v, hi, lo);
    ((uint2*)g_whi)[i] = hi;
    ((uint2*)g_wlo)[i] = lo;
}
__global__ void convert_wp(const float* __restrict__ src) {
    int i = blockIdx.x * blockDim.x + threadIdx.x;
    float4 v = ((const float4*)src)[i];
    uint2 hi, lo; split4(v, hi, lo);
    ((uint2*)g_wphi)[i] = hi;
    ((uint2*)g_wplo)[i] = lo;
}

// ---------------------------------------------------------------------------
// GEMM: 128x128 CTA tile, 512 threads, 16 warps (4x4, M32xN32/warp),
// K-chunk 64, cp.async double-buffered, ldmatrix loads.
// ---------------------------------------------------------------------------
#define GS 72
#define SBY (GS * 2)

// 3-pass stage (qkv): Ahi 0 | Alo 18432 | Bhi 36864 | Blo 55296 (bytes)
#define G3_STAGE_B 73728
#define GEMM3_SMEM (2 * G3_STAGE_B)    // 147456 B

// 2-pass stage (proj): Ahi 0 | Bhi 18432 | Blo 36864 (bytes)
#define G2_STAGE_B 55296
#define GEMM2_SMEM (2 * G2_STAGE_B)    // 110592 B

__device__ __forceinline__ void gemm_step3(
    uint32_t sA, float acc[2][4][4], int wm, int wn, int lane)
{
    uint32_t cch[2][4][2];
#pragma unroll
    for (int i = 0; i < 2; i++)
#pragma unroll
        for (int j = 0; j < 4; j++) { cch[i][j][0] = 0u; cch[i][j][1] = 0u; }

#pragma unroll
    for (int ks = 0; ks < 4; ks++) {
        const int k0 = ks * 16;
        uint32_t bh0[4], bh1[4], bl0[4], bl1[4];
        uint32_t ba0 = b_addr(sA + 36864, wn * 32,      k0, SBY, lane);
        uint32_t ba1 = b_addr(sA + 36864, wn * 32 + 16, k0, SBY, lane);
        ldsm_x4(bh0, ba0);
        ldsm_x4(bh1, ba1);
        ldsm_x4(bl0, ba0 + 18432);
        ldsm_x4(bl1, ba1 + 18432);
#pragma unroll
        for (int mt = 0; mt < 2; mt++) {
            uint32_t ah[4], al[4];
            uint32_t aa = a_addr(sA, wm * 32 + mt * 16, k0, SBY, lane);
            ldsm_x4(ah, aa);
            ldsm_x4(al, aa + 18432);
            mma_f32acc(acc[mt][0], ah, bh0 + 0);
            mma_f32acc(acc[mt][1], ah, bh0 + 2);
            mma_f32acc(acc[mt][2], ah, bh1 + 0);
            mma_f32acc(acc[mt][3], ah, bh1 + 2);
            mma_f16acc(cch[mt][0], ah, bl0 + 0);
            mma_f16acc(cch[mt][1], ah, bl0 + 2);
            mma_f16acc(cch[mt][2], ah, bl1 + 0);
            mma_f16acc(cch[mt][3], ah, bl1 + 2);
            mma_f16acc(cch[mt][0], al, bh0 + 0);
            mma_f16acc(cch[mt][1], al, bh0 + 2);
            mma_f16acc(cch[mt][2], al, bh1 + 0);
            mma_f16acc(cch[mt][3], al, bh1 + 2);
        }
    }
#pragma unroll
    for (int i = 0; i < 2; i++)
#pragma unroll
        for (int j = 0; j < 4; j++) addcross(acc[i][j], cch[i][j]);
}

__device__ __forceinline__ void gemm_step2(
    uint32_t sA, float acc[2][4][4], int wm, int wn, int lane)
{
    uint32_t cch[2][4][2];
#pragma unroll
    for (int i = 0; i < 2; i++)
#pragma unroll
        for (int j = 0; j < 4; j++) { cch[i][j][0] = 0u; cch[i][j][1] = 0u; }

#pragma unroll
    for (int ks = 0; ks < 4; ks++) {
        const int k0 = ks * 16;
        uint32_t bh0[4], bh1[4], bl0[4], bl1[4];
        uint32_t ba0 = b_addr(sA + 18432, wn * 32,      k0, SBY, lane);
        uint32_t ba1 = b_addr(sA + 18432, wn * 32 + 16, k0, SBY, lane);
        ldsm_x4(bh0, ba0);
        ldsm_x4(bh1, ba1);
        ldsm_x4(bl0, ba0 + 18432);
        ldsm_x4(bl1, ba1 + 18432);
#pragma unroll
        for (int mt = 0; mt < 2; mt++) {
            uint32_t ah[4];
            ldsm_x4(ah, a_addr(sA, wm * 32 + mt * 16, k0, SBY, lane));
            mma_f32acc(acc[mt][0], ah, bh0 + 0);
            mma_f32acc(acc[mt][1], ah, bh0 + 2);
            mma_f32acc(acc[mt][2], ah, bh1 + 0);
            mma_f32acc(acc[mt][3], ah, bh1 + 2);
            mma_f16acc(cch[mt][0], ah, bl0 + 0);
            mma_f16acc(cch[mt][1], ah, bl0 + 2);
            mma_f16acc(cch[mt][2], ah, bl1 + 0);
            mma_f16acc(cch[mt][3], ah, bl1 + 2);
        }
    }
#pragma unroll
    for (int i = 0; i < 2; i++)
#pragma unroll
        for (int j = 0; j < 4; j++) addcross(acc[i][j], cch[i][j]);
}

// ---------------------------------------------------------------------------
// QKV GEMM (3-pass): x[4096,1024] @ wqkv[3072,1024]^T
// ---------------------------------------------------------------------------
__global__ void __launch_bounds__(512, 1)
tc_gemm_qkv()
{
    extern __shared__ __half smg[];
    const uint32_t sbase = smem_u32(smg);
    const int tid = threadIdx.x;
    const int wid = tid >> 5, lane = tid & 31;
    const int grp = lane >> 2, qd = lane & 3;
    const int wm = wid >> 2, wn = wid & 3;
    const int row0 = blockIdx.y * 128, col0 = blockIdx.x * 128;

    auto stage_load = [&](int s, int kb) {
        uint32_t so = sbase + (uint32_t)(s * G3_STAGE_B);
#pragma unroll
        for (int it = 0; it < 2; it++) {
            int f = tid + 512 * it;
            int row = f >> 3, q = f & 7;
            size_t asrc = (size_t)(row0 + row) * CDIM + kb * 64 + q * 8;
            uint32_t off = so + (uint32_t)(row * GS + q * 8) * 2;
            cp16(off,         g_xhi + asrc);
            cp16(off + 18432, g_xlo + asrc);
        }
#pragma unroll
        for (int it = 0; it < 2; it++) {
            int f = tid + 512 * it;
            int row = f >> 3, q = f & 7;
            size_t bsrc = (size_t)(col0 + row) * CDIM + kb * 64 + q * 8;
            uint32_t off = so + 36864 + (uint32_t)(row * GS + q * 8) * 2;
            cp16(off,         g_whi + bsrc);
            cp16(off + 18432, g_wlo + bsrc);
        }
    };

    float acc[2][4][4];
#pragma unroll
    for (int i = 0; i < 2; i++)
#pragma unroll
        for (int j = 0; j < 4; j++)
#pragma unroll
            for (int t = 0; t < 4; t++) acc[i][j][t] = 0.f;

    stage_load(0, 0); CP_COMMIT();

    for (int kb = 0; kb < 16; kb++) {
        CP_WAIT(0);
        __syncthreads();
        if (kb < 15) { stage_load((kb + 1) & 1, kb + 1); CP_COMMIT(); }
        gemm_step3(sbase + (uint32_t)((kb & 1) * G3_STAGE_B), acc, wm, wn, lane);
    }

    // epilogue: q -> g_qhi (plain fp16, scaled); k -> split; v -> g_vhi (transposed)
#pragma unroll
    for (int mt = 0; mt < 2; mt++) {
        int r = row0 + wm * 32 + mt * 16 + grp;
        int b0 = r >> 11, n0 = r & 2047;
#pragma unroll
        for (int nt = 0; nt < 4; nt++) {
            int c3 = col0 + wn * 32 + nt * 8 + qd * 2;
            int which = c3 >> 10;
            int cc = c3 & 1023;
            int hh = cc >> 6;
            int d = cc & 63;
            float mul = (which == 0) ? QSCALE : 1.0f;
            float* a4 = acc[mt][nt];
            float v0 = a4[0] * mul, v1 = a4[1] * mul;
            float v2 = a4[2] * mul, v3 = a4[3] * mul;
            size_t head = ((size_t)b0 * HN + hh) * (size_t)NSEQ * DH;
            if (which == 0) {
                size_t idx = head + (size_t)n0 * DH + d;
                *(uint32_t*)(g_qhi + idx) =
                    h2u(__float2half_rn(v0), __float2half_rn(v1));
                *(uint32_t*)(g_qhi + idx + 8 * DH) =
                    h2u(__float2half_rn(v2), __float2half_rn(v3));
            } else if (which == 1) {
                __half h0, h1, h2, h3, l0, l1, l2, l3;
                splitf(v0, h0, l0); splitf(v1, h1, l1);
                splitf(v2, h2, l2); splitf(v3, h3, l3);
                size_t idx = head + (size_t)n0 * DH + d;
                *(uint32_t*)(g_khi + idx) = h2u(h0, h1);
                *(uint32_t*)(g_klo + idx) = h2u(l0, l1);
                *(uint32_t*)(g_khi + idx + 8 * DH) = h2u(h2, h3);
                *(uint32_t*)(g_klo + idx + 8 * DH) = h2u(l2, l3);
            } else {
                size_t idx = head + (size_t)d * NSEQ + n0;
                g_vhi[idx] = __float2half_rn(v0);
                g_vhi[idx + NSEQ] = __float2half_rn(v1);
                g_vhi[idx + 8] = __float2half_rn(v2);
                g_vhi[idx + NSEQ + 8] = __float2half_rn(v3);
            }
        }
    }
}

// ---------------------------------------------------------------------------
// Output projection GEMM (2-pass): avhi @ (wphi + wplo)
// ---------------------------------------------------------------------------
__global__ void __launch_bounds__(512, 1)
tc_gemm_proj(float* __restrict__ Cout)
{
    extern __shared__ __half smg[];
    const uint32_t sbase = smem_u32(smg);
    const int tid = threadIdx.x;
    const int wid = tid >> 5, lane = tid & 31;
    const int grp = lane >> 2, qd = lane & 3;
    const int wm = wid >> 2, wn = wid & 3;
    const int row0 = blockIdx.y * 128, col0 = blockIdx.x * 128;

    auto stage_load = [&](int s, int kb) {
        uint32_t so = sbase + (uint32_t)(s * G2_STAGE_B);
#pragma unroll
        for (int it = 0; it < 2; it++) {
            int f = tid + 512 * it;
            int row = f >> 3, q = f & 7;
            size_t asrc = (size_t)(row0 + row) * CDIM + kb * 64 + q * 8;
            cp16(so + (uint32_t)(row * GS + q * 8) * 2, g_avhi + asrc);
        }
#pragma unroll
        for (int it = 0; it < 2; it++) {
            int f = tid + 512 * it;
            int row = f >> 3, q = f & 7;
            size_t bsrc = (size_t)(col0 + row) * CDIM + kb * 64 + q * 8;
            uint32_t off = so + 18432 + (uint32_t)(row * GS + q * 8) * 2;
            cp16(off,         g_wphi + bsrc);
            cp16(off + 18432, g_wplo + bsrc);
        }
    };

    float acc[2][4][4];
#pragma unroll
    for (int i = 0; i < 2; i++)
#pragma unroll
        for (int j = 0; j < 4; j++)
#pragma unroll
            for (int t = 0; t < 4; t++) acc[i][j][t] = 0.f;

    stage_load(0, 0); CP_COMMIT();

    for (int kb = 0; kb < 16; kb++) {
        CP_WAIT(0);
        __syncthreads();
        if (kb < 15) { stage_load((kb + 1) & 1, kb + 1); CP_COMMIT(); }
        gemm_step2(sbase + (uint32_t)((kb & 1) * G2_STAGE_B), acc, wm, wn, lane);
    }

#pragma unroll
    for (int mt = 0; mt < 2; mt++) {
        int r = row0 + wm * 32 + mt * 16 + grp;
#pragma unroll
        for (int nt = 0; nt < 4; nt++) {
            int cl = col0 + wn * 32 + nt * 8 + qd * 2;
            float* a4 = acc[mt][nt];
            float2 v0 = {a4[0], a4[1]};
            float2 v1 = {a4[2], a4[3]};
            *(float2*)(Cout + (size_t)r * CDIM + cl) = v0;
            *(float2*)(Cout + (size_t)(r + 8) * CDIM + cl) = v1;
        }
    }
}

// ---------------------------------------------------------------------------
// Fused sigmoid attention: 128 q-rows per CTA, 64-key tiles, 2 CTAs/SM.
// S: 2-pass (qh·kh f32 + qh·kl f16).  PV: 1-pass (p·vh f32).
// smem (halfs): Qhi 0..9216 | K stage s @9216+s*9216 (hi 4608 + lo 4608)
//               | V stage s @27648+s*4608 (hi only). Total 36864 halfs.
// ---------------------------------------------------------------------------
#define AK_BASE 9216
#define AV_BASE 27648
#define ATTN_SMEM (36864 * 2)    // 73728 B

__global__ void __launch_bounds__(256, 2)
attn_kernel2(float* __restrict__ attn_out, float* __restrict__ av_out)
{
    extern __shared__ __half sma[];
    const uint32_t sbase = smem_u32(sma);
    const int tid = threadIdx.x;
    const int wid = tid >> 5, lane = tid & 31;
    const int grp = lane >> 2, qd = lane & 3;
    const int row0 = blockIdx.x * 128;
    const int bhid = blockIdx.y;
    const int b = bhid >> 4, h = bhid & 15;
    const size_t head = ((size_t)b * HN + h) * (size_t)NSEQ * DH;

    auto load_kv = [&](int jt_, int s) {
        uint32_t ko = sbase + (uint32_t)(AK_BASE + s * 9216) * 2;
        uint32_t vo = sbase + (uint32_t)(AV_BASE + s * 4608) * 2;
#pragma unroll
        for (int it = 0; it < 2; it++) {
            int f = tid + 256 * it;
            int row = f >> 3, q = f & 7;
            {   // K tile: hi + lo
                size_t src = head + (size_t)(jt_ * 64 + row) * DH + q * 8;
                uint32_t off = ko + (uint32_t)(row * GS + q * 8) * 2;
                cp16(off,            g_khi + src);
                cp16(off + 4608 * 2, g_klo + src);
            }
            {   // V^T tile: hi only
                size_t src = head + (size_t)row * NSEQ + (size_t)jt_ * 64 + q * 8;
                cp16(vo + (uint32_t)(row * GS + q * 8) * 2, g_vhi + src);
            }
        }
    };

    // prologue: Q (128x64, hi only) + tile 0
#pragma unroll
    for (int it = 0; it < 4; it++) {
        int f = tid + 256 * it;
        int row = f >> 3, q = f & 7;
        size_t src = head + (size_t)(row0 + row) * DH + q * 8;
        cp16(sbase + (uint32_t)(row * GS + q * 8) * 2, g_qhi + src);
    }
    load_kv(0, 0);
    CP_COMMIT();

    float oacc[8][4];
#pragma unroll
    for (int i = 0; i < 8; i++)
#pragma unroll
        for (int t = 0; t < 4; t++) oacc[i][t] = 0.f;

    for (int jt = 0; jt < NSEQ / 64; jt++) {
        CP_WAIT(0);
        __syncthreads();
        if (jt < NSEQ / 64 - 1) { load_kv(jt + 1, (jt + 1) & 1); CP_COMMIT(); }

        const uint32_t kb = sbase + (uint32_t)(AK_BASE + (jt & 1) * 9216) * 2;
        const uint32_t vb = sbase + (uint32_t)(AV_BASE + (jt & 1) * 4608) * 2;

        // ---- S = Q K^T (2-pass) ----
        float sacc[8][4];
        uint32_t sch[8][2];
#pragma unroll
        for (int i = 0; i < 8; i++) {
#pragma unroll
            for (int t = 0; t < 4; t++) sacc[i][t] = 0.f;
            sch[i][0] = 0u; sch[i][1] = 0u;
        }

#pragma unroll
        for (int ks = 0; ks < 4; ks++) {
            const int k0 = ks * 16;
            uint32_t qfh[4];
            ldsm_x4(qfh, a_addr(sbase, wid * 16, k0, SBY, lane));
#pragma unroll
            for (int t = 0; t < 4; t++) {
                uint32_t kh4[4], kl4[4];
                uint32_t kaddr = b_addr(kb, t * 16, k0, SBY, lane);
                ldsm_x4(kh4, kaddr);
                ldsm_x4(kl4, kaddr + 9216);
                mma_f32acc(sacc[2 * t],     qfh, kh4 + 0);
                mma_f32acc(sacc[2 * t + 1], qfh, kh4 + 2);
                mma_f16acc(sch[2 * t],      qfh, kl4 + 0);
                mma_f16acc(sch[2 * t + 1],  qfh, kl4 + 2);
            }
        }
#pragma unroll
        for (int i = 0; i < 8; i++) addcross(sacc[i], sch[i]);

        // ---- sigmoid + attn store + P (plain fp16) -> PV (1-pass) ----
        float* ab = attn_out
            ? attn_out + ((size_t)bhid * NSEQ + row0 + wid * 16 + grp) * NSEQ
                       + (size_t)jt * 64
            : nullptr;

#pragma unroll
        for (int kc = 0; kc < 4; kc++) {
            float* c0 = sacc[2 * kc];
            float* c1 = sacc[2 * kc + 1];
            float p0 = __fdividef(1.f, 1.f + __expf(-(c0[0] + ATTN_BIAS_F)));
            float p1 = __fdividef(1.f, 1.f + __expf(-(c0[1] + ATTN_BIAS_F)));
            float p2 = __fdividef(1.f, 1.f + __expf(-(c0[2] + ATTN_BIAS_F)));
            float p3 = __fdividef(1.f, 1.f + __expf(-(c0[3] + ATTN_BIAS_F)));
            float p4 = __fdividef(1.f, 1.f + __expf(-(c1[0] + ATTN_BIAS_F)));
            float p5 = __fdividef(1.f, 1.f + __expf(-(c1[1] + ATTN_BIAS_F)));
            float p6 = __fdividef(1.f, 1.f + __expf(-(c1[2] + ATTN_BIAS_F)));
            float p7 = __fdividef(1.f, 1.f + __expf(-(c1[3] + ATTN_BIAS_F)));
            if (ab) {
                float2 w0 = {p0, p1}, w1 = {p2, p3}, w2 = {p4, p5}, w3 = {p6, p7};
                *(float2*)(ab + kc * 16 + 2 * qd) = w0;
                *(float2*)(ab + 8 * NSEQ + kc * 16 + 2 * qd) = w1;
                *(float2*)(ab + kc * 16 + 8 + 2 * qd) = w2;
                *(float2*)(ab + 8 * NSEQ + kc * 16 + 8 + 2 * qd) = w3;
            }
            uint32_t pah[4] = {
                h2u(__float2half_rn(p0), __float2half_rn(p1)),
                h2u(__float2half_rn(p2), __float2half_rn(p3)),
                h2u(__float2half_rn(p4), __float2half_rn(p5)),
                h2u(__float2half_rn(p6), __float2half_rn(p7)) };
#pragma unroll
            for (int t = 0; t < 4; t++) {
                uint32_t vh4[4];
                ldsm_x4(vh4, b_addr(vb, t * 16, kc * 16, SBY, lane));
                mma_f32acc(oacc[2 * t],     pah, vh4 + 0);
                mma_f32acc(oacc[2 * t + 1], pah, vh4 + 2);
            }
        }
    }

    // ---- epilogue: O -> fp32 av_out + fp16 g_avhi ----
    const int r = row0 + wid * 16 + grp;
#pragma unroll
    for (int dt = 0; dt < 8; dt++) {
        int d = dt * 8 + qd * 2;
        size_t base = (((size_t)b * NSEQ + r) * HN + h) * DH + d;
        float2 v0 = {oacc[dt][0], oacc[dt][1]};
        float2 v1 = {oacc[dt][2], oacc[dt][3]};
        *(float2*)(av_out + base) = v0;
        *(float2*)(av_out + base + 8 * (size_t)CDIM) = v1;
        *(uint32_t*)(g_avhi + base) =
            h2u(__float2half_rn(v0.x), __float2half_rn(v0.y));
        *(uint32_t*)(g_avhi + base + 8 * (size_t)CDIM) =
            h2u(__float2half_rn(v1.x), __float2half_rn(v1.y));
    }
}

// ---------------------------------------------------------------------------
// Launch
// ---------------------------------------------------------------------------
extern "C" void kernel_launch(void* const* d_in, const int* in_sizes, int n_in,
                              void* d_out, int out_size)
{
    const float* x     = (const float*)d_in[0];
    const float* wqkv  = (const float*)d_in[1];
    const float* wproj = (const float*)d_in[2];
    float* out = (float*)d_out;

    const size_t SZ_ATTN = (size_t)BSZ * HN * NSEQ * NSEQ;
    const size_t SZ_AV   = (size_t)BSZ * NSEQ * CDIM;
    const bool full = ((size_t)out_size >= SZ_ATTN + 2 * SZ_AV);

    static float* g_av_dev = nullptr;
    static bool attr_done = false;
    if (!attr_done) {
        cudaFuncSetAttribute(tc_gemm_qkv,
                             cudaFuncAttributeMaxDynamicSharedMemorySize, GEMM3_SMEM);
        cudaFuncSetAttribute(attn_kernel2,
                             cudaFuncAttributeMaxDynamicSharedMemorySize, ATTN_SMEM);
        cudaFuncSetAttribute(tc_gemm_proj,
                             cudaFuncAttributeMaxDynamicSharedMemorySize, GEMM2_SMEM);
        cudaGetSymbolAddress((void**)&g_av_dev, g_av);
        attr_done = true;
    }

    // 0) split-convert inputs
    convert_x<<<(int)(NELEM_X / 4 / 256), 256>>>(x);
    convert_w<<<(int)(NELEM_W / 4 / 256), 256>>>(wqkv);
    convert_wp<<<(int)(NELEM_WP / 4 / 256), 256>>>(wproj);

    // 1) QKV projection (3-pass) -> q fp16 (scaled), k split, v^T fp16
    tc_gemm_qkv<<<dim3(3 * CDIM / 128, (BSZ * NSEQ) / 128), 512, GEMM3_SMEM>>>();

    // 2) Fused sigmoid attention (S 2-pass, PV 1-pass)
    float* attn_dst = full ? out : nullptr;
    float* av_dst   = full ? out + SZ_ATTN : g_av_dev;
    attn_kernel2<<<dim3(NSEQ / 128, BSZ * HN), 256, ATTN_SMEM>>>(attn_dst, av_dst);

    // 3) Output projection (2-pass)
    float* proj_dst = full ? out + SZ_ATTN + SZ_AV : out;
    tc_gemm_proj<<<dim3(CDIM / 128, (BSZ * NSEQ) / 128), 512, GEMM2_SMEM>>>(proj_dst);
}

// round 16
// speedup vs baseline: 1.4115x; 1.0964x over previous
#include <cuda_runtime.h>
#include <cuda_fp16.h>
#include <cstdint>
#include <cstddef>

// Problem constants
#define BSZ   2
#define NSEQ  2048
#define CDIM  1024
#define HN    16
#define DH    64
#define QSCALE 0.125f
#define ATTN_BIAS_F (-7.625f)

#define NELEM_X   ((size_t)BSZ * NSEQ * CDIM)
#define NELEM_W   ((size_t)3 * CDIM * CDIM)
#define NELEM_WP  ((size_t)CDIM * CDIM)
#define NELEM_HD  ((size_t)BSZ * HN * NSEQ * DH)

__device__ __half g_xhi[NELEM_X],  g_xlo[NELEM_X];
__device__ __half g_whi[NELEM_W],  g_wlo[NELEM_W];
__device__ __half g_wphi[NELEM_WP], g_wplo[NELEM_WP];
__device__ __half g_qhi[NELEM_HD];                    // q: plain fp16 (scaled)
__device__ __half g_khi[NELEM_HD], g_klo[NELEM_HD];   // k: split
__device__ __half g_vhi[NELEM_HD];                    // v^T: plain fp16
__device__ __half g_avhi[NELEM_X];                    // av: plain fp16
__device__ float g_av[NELEM_X];

// ---------------------------------------------------------------------------
// Helpers
// ---------------------------------------------------------------------------
__device__ __forceinline__ uint32_t smem_u32(const void* p) {
    uint32_t a;
    asm("{ .reg .u64 t; cvta.to.shared.u64 t, %1; cvt.u32.u64 %0, t; }"
        : "=r"(a) : "l"(p));
    return a;
}

__device__ __forceinline__ void mma_f32acc(float c[4], const uint32_t a[4],
                                           const uint32_t b[2]) {
    asm volatile(
        "mma.sync.aligned.m16n8k16.row.col.f32.f16.f16.f32 "
        "{%0,%1,%2,%3}, {%4,%5,%6,%7}, {%8,%9}, {%0,%1,%2,%3};\n"
        : "+f"(c[0]), "+f"(c[1]), "+f"(c[2]), "+f"(c[3])
        : "r"(a[0]), "r"(a[1]), "r"(a[2]), "r"(a[3]), "r"(b[0]), "r"(b[1]));
}
__device__ __forceinline__ void mma_f16acc(uint32_t c[2], const uint32_t a[4],
                                           const uint32_t b[2]) {
    asm volatile(
        "mma.sync.aligned.m16n8k16.row.col.f16.f16.f16.f16 "
        "{%0,%1}, {%2,%3,%4,%5}, {%6,%7}, {%0,%1};\n"
        : "+r"(c[0]), "+r"(c[1])
        : "r"(a[0]), "r"(a[1]), "r"(a[2]), "r"(a[3]), "r"(b[0]), "r"(b[1]));
}
__device__ __forceinline__ void addcross(float c[4], const uint32_t ch[2]) {
    float2 v0 = __half22float2(*(const __half2*)&ch[0]);
    float2 v1 = __half22float2(*(const __half2*)&ch[1]);
    c[0] += v0.x; c[1] += v0.y; c[2] += v1.x; c[3] += v1.y;
}

__device__ __forceinline__ void ldsm_x4(uint32_t r[4], uint32_t addr) {
    asm volatile("ldmatrix.sync.aligned.m8n8.x4.shared.b16 {%0,%1,%2,%3}, [%4];"
                 : "=r"(r[0]), "=r"(r[1]), "=r"(r[2]), "=r"(r[3]) : "r"(addr));
}
__device__ __forceinline__ uint32_t a_addr(uint32_t base, int row0, int k0,
                                           int SB, int lane) {
    int mat = lane >> 3, r = lane & 7;
    int row = row0 + r + ((mat & 1) << 3);
    int k   = k0 + ((mat >> 1) << 3);
    return base + row * SB + k * 2;
}
__device__ __forceinline__ uint32_t b_addr(uint32_t base, int n0, int k0,
                                           int SB, int lane) {
    int mat = lane >> 3, r = lane & 7;
    int row = n0 + r + ((mat >> 1) << 3);
    int k   = k0 + ((mat & 1) << 3);
    return base + row * SB + k * 2;
}

__device__ __forceinline__ void splitf(float v, __half& h, __half& l) {
    h = __float2half_rn(v);
    l = __float2half_rn(v - __half2float(h));
}
__device__ __forceinline__ uint32_t h2u(__half a, __half b) {
    __half2 t = __halves2half2(a, b);
    return *reinterpret_cast<uint32_t*>(&t);
}
__device__ __forceinline__ void split4(float4 v, uint2& hi, uint2& lo) {
    __half h0, h1, h2, h3, l0, l1, l2, l3;
    splitf(v.x, h0, l0); splitf(v.y, h1, l1);
    splitf(v.z, h2, l2); splitf(v.w, h3, l3);
    hi.x = h2u(h0, h1); hi.y = h2u(h2, h3);
    lo.x = h2u(l0, l1); lo.y = h2u(l2, l3);
}

__device__ __forceinline__ void cp16(uint32_t dst, const void* src) {
    asm volatile("cp.async.cg.shared.global [%0], [%1], 16;" :: "r"(dst), "l"(src));
}
#define CP_COMMIT() asm volatile("cp.async.commit_group;" ::: "memory")
#define CP_WAIT(N)  asm volatile("cp.async.wait_group %0;" :: "n"(N) : "memory")

// ---------------------------------------------------------------------------
// Elementwise split converters
// ---------------------------------------------------------------------------
__global__ void convert_x(const float* __restrict__ src) {
    int i = blockIdx.x * blockDim.x + threadIdx.x;
    float4 v = ((const float4*)src)[i];
    uint2 hi, lo; split4(v, hi, lo);
    ((uint2*)g_xhi)[i] = hi;
    ((uint2*)g_xlo)[i] = lo;
}
__global__ void convert_w(const float* __restrict__ src) {
    int i = blockIdx.x * blockDim.x + threadIdx.x;
    float4 v = ((const float4*)src)[i];
    uint2 hi, lo; split4(v, hi, lo);
    ((uint2*)g_whi)[i] = hi;
    ((uint2*)g_wlo)[i] = lo;
}
__global__ void convert_wp(const float* __restrict__ src) {
    int i = blockIdx.x * blockDim.x + threadIdx.x;
    float4 v = ((const float4*)src)[i];
    uint2 hi, lo; split4(v, hi, lo);
    ((uint2*)g_wphi)[i] = hi;
    ((uint2*)g_wplo)[i] = lo;
}

// ---------------------------------------------------------------------------
// GEMM: 128x128 CTA tile, 512 threads, 16 warps (4x4, M32xN32/warp),
// K-chunk 64, cp.async double-buffered, ldmatrix loads.
// ---------------------------------------------------------------------------
#define GS 72
#define SBY (GS * 2)

// qkv stage: Ahi 0 | Alo 18432 | Bhi 36864 | Blo 55296 (bytes)
#define G3_STAGE_B 73728
#define GEMM3_SMEM (2 * G3_STAGE_B)    // 147456 B

// proj stage: Ahi 0 | Bhi 18432 | Blo 36864 (bytes)
#define G2_STAGE_B 55296
#define GEMM2_SMEM (2 * G2_STAGE_B)    // 110592 B

// 3-pass: (Ahi+Alo)·(Bhi+Blo) dropping Alo·Blo   [K block]
__device__ __forceinline__ void gemm_step3(
    uint32_t sA, float acc[2][4][4], int wm, int wn, int lane)
{
    uint32_t cch[2][4][2];
#pragma unroll
    for (int i = 0; i < 2; i++)
#pragma unroll
        for (int j = 0; j < 4; j++) { cch[i][j][0] = 0u; cch[i][j][1] = 0u; }

#pragma unroll
    for (int ks = 0; ks < 4; ks++) {
        const int k0 = ks * 16;
        uint32_t bh0[4], bh1[4], bl0[4], bl1[4];
        uint32_t ba0 = b_addr(sA + 36864, wn * 32,      k0, SBY, lane);
        uint32_t ba1 = b_addr(sA + 36864, wn * 32 + 16, k0, SBY, lane);
        ldsm_x4(bh0, ba0);
        ldsm_x4(bh1, ba1);
        ldsm_x4(bl0, ba0 + 18432);
        ldsm_x4(bl1, ba1 + 18432);
#pragma unroll
        for (int mt = 0; mt < 2; mt++) {
            uint32_t ah[4], al[4];
            uint32_t aa = a_addr(sA, wm * 32 + mt * 16, k0, SBY, lane);
            ldsm_x4(ah, aa);
            ldsm_x4(al, aa + 18432);
            mma_f32acc(acc[mt][0], ah, bh0 + 0);
            mma_f32acc(acc[mt][1], ah, bh0 + 2);
            mma_f32acc(acc[mt][2], ah, bh1 + 0);
            mma_f32acc(acc[mt][3], ah, bh1 + 2);
            mma_f16acc(cch[mt][0], ah, bl0 + 0);
            mma_f16acc(cch[mt][1], ah, bl0 + 2);
            mma_f16acc(cch[mt][2], ah, bl1 + 0);
            mma_f16acc(cch[mt][3], ah, bl1 + 2);
            mma_f16acc(cch[mt][0], al, bh0 + 0);
            mma_f16acc(cch[mt][1], al, bh0 + 2);
            mma_f16acc(cch[mt][2], al, bh1 + 0);
            mma_f16acc(cch[mt][3], al, bh1 + 2);
        }
    }
#pragma unroll
    for (int i = 0; i < 2; i++)
#pragma unroll
        for (int j = 0; j < 4; j++) addcross(acc[i][j], cch[i][j]);
}

// 2-pass on qkv layout: Ahi·(Bhi+Blo)   [Q and V blocks]
__device__ __forceinline__ void gemm_step2_qv(
    uint32_t sA, float acc[2][4][4], int wm, int wn, int lane)
{
    uint32_t cch[2][4][2];
#pragma unroll
    for (int i = 0; i < 2; i++)
#pragma unroll
        for (int j = 0; j < 4; j++) { cch[i][j][0] = 0u; cch[i][j][1] = 0u; }

#pragma unroll
    for (int ks = 0; ks < 4; ks++) {
        const int k0 = ks * 16;
        uint32_t bh0[4], bh1[4], bl0[4], bl1[4];
        uint32_t ba0 = b_addr(sA + 36864, wn * 32,      k0, SBY, lane);
        uint32_t ba1 = b_addr(sA + 36864, wn * 32 + 16, k0, SBY, lane);
        ldsm_x4(bh0, ba0);
        ldsm_x4(bh1, ba1);
        ldsm_x4(bl0, ba0 + 18432);
        ldsm_x4(bl1, ba1 + 18432);
#pragma unroll
        for (int mt = 0; mt < 2; mt++) {
            uint32_t ah[4];
            ldsm_x4(ah, a_addr(sA, wm * 32 + mt * 16, k0, SBY, lane));
            mma_f32acc(acc[mt][0], ah, bh0 + 0);
            mma_f32acc(acc[mt][1], ah, bh0 + 2);
            mma_f32acc(acc[mt][2], ah, bh1 + 0);
            mma_f32acc(acc[mt][3], ah, bh1 + 2);
            mma_f16acc(cch[mt][0], ah, bl0 + 0);
            mma_f16acc(cch[mt][1], ah, bl0 + 2);
            mma_f16acc(cch[mt][2], ah, bl1 + 0);
            mma_f16acc(cch[mt][3], ah, bl1 + 2);
        }
    }
#pragma unroll
    for (int i = 0; i < 2; i++)
#pragma unroll
        for (int j = 0; j < 4; j++) addcross(acc[i][j], cch[i][j]);
}

// 2-pass on proj layout: Ahi 0 | Bhi 18432 | Blo 36864
__device__ __forceinline__ void gemm_step2(
    uint32_t sA, float acc[2][4][4], int wm, int wn, int lane)
{
    uint32_t cch[2][4][2];
#pragma unroll
    for (int i = 0; i < 2; i++)
#pragma unroll
        for (int j = 0; j < 4; j++) { cch[i][j][0] = 0u; cch[i][j][1] = 0u; }

#pragma unroll
    for (int ks = 0; ks < 4; ks++) {
        const int k0 = ks * 16;
        uint32_t bh0[4], bh1[4], bl0[4], bl1[4];
        uint32_t ba0 = b_addr(sA + 18432, wn * 32,      k0, SBY, lane);
        uint32_t ba1 = b_addr(sA + 18432, wn * 32 + 16, k0, SBY, lane);
        ldsm_x4(bh0, ba0);
        ldsm_x4(bh1, ba1);
        ldsm_x4(bl0, ba0 + 18432);
        ldsm_x4(bl1, ba1 + 18432);
#pragma unroll
        for (int mt = 0; mt < 2; mt++) {
            uint32_t ah[4];
            ldsm_x4(ah, a_addr(sA, wm * 32 + mt * 16, k0, SBY, lane));
            mma_f32acc(acc[mt][0], ah, bh0 + 0);
            mma_f32acc(acc[mt][1], ah, bh0 + 2);
            mma_f32acc(acc[mt][2], ah, bh1 + 0);
            mma_f32acc(acc[mt][3], ah, bh1 + 2);
            mma_f16acc(cch[mt][0], ah, bl0 + 0);
            mma_f16acc(cch[mt][1], ah, bl0 + 2);
            mma_f16acc(cch[mt][2], ah, bl1 + 0);
            mma_f16acc(cch[mt][3], ah, bl1 + 2);
        }
    }
#pragma unroll
    for (int i = 0; i < 2; i++)
#pragma unroll
        for (int j = 0; j < 4; j++) addcross(acc[i][j], cch[i][j]);
}

// ---------------------------------------------------------------------------
// QKV GEMM: K-block 3-pass (split output), Q/V blocks 2-pass (fp16 output)
// ---------------------------------------------------------------------------
__global__ void __launch_bounds__(512, 1)
tc_gemm_qkv()
{
    extern __shared__ __half smg[];
    const uint32_t sbase = smem_u32(smg);
    const int tid = threadIdx.x;
    const int wid = tid >> 5, lane = tid & 31;
    const int grp = lane >> 2, qd = lane & 3;
    const int wm = wid >> 2, wn = wid & 3;
    const int row0 = blockIdx.y * 128, col0 = blockIdx.x * 128;
    const int which = col0 >> 10;          // 0=q, 1=k, 2=v (uniform per CTA)
    const bool kblock = (which == 1);

    auto stage_load = [&](int s, int kb) {
        uint32_t so = sbase + (uint32_t)(s * G3_STAGE_B);
#pragma unroll
        for (int it = 0; it < 2; it++) {
            int f = tid + 512 * it;
            int row = f >> 3, q = f & 7;
            size_t asrc = (size_t)(row0 + row) * CDIM + kb * 64 + q * 8;
            uint32_t off = so + (uint32_t)(row * GS + q * 8) * 2;
            cp16(off, g_xhi + asrc);
            if (kblock) cp16(off + 18432, g_xlo + asrc);
        }
#pragma unroll
        for (int it = 0; it < 2; it++) {
            int f = tid + 512 * it;
            int row = f >> 3, q = f & 7;
            size_t bsrc = (size_t)(col0 + row) * CDIM + kb * 64 + q * 8;
            uint32_t off = so + 36864 + (uint32_t)(row * GS + q * 8) * 2;
            cp16(off,         g_whi + bsrc);
            cp16(off + 18432, g_wlo + bsrc);
        }
    };

    float acc[2][4][4];
#pragma unroll
    for (int i = 0; i < 2; i++)
#pragma unroll
        for (int j = 0; j < 4; j++)
#pragma unroll
            for (int t = 0; t < 4; t++) acc[i][j][t] = 0.f;

    stage_load(0, 0); CP_COMMIT();

    for (int kb = 0; kb < 16; kb++) {
        CP_WAIT(0);
        __syncthreads();
        if (kb < 15) { stage_load((kb + 1) & 1, kb + 1); CP_COMMIT(); }
        uint32_t sA = sbase + (uint32_t)((kb & 1) * G3_STAGE_B);
        if (kblock) gemm_step3(sA, acc, wm, wn, lane);
        else        gemm_step2_qv(sA, acc, wm, wn, lane);
    }

    // epilogue
#pragma unroll
    for (int mt = 0; mt < 2; mt++) {
        int r = row0 + wm * 32 + mt * 16 + grp;
        int b0 = r >> 11, n0 = r & 2047;
#pragma unroll
        for (int nt = 0; nt < 4; nt++) {
            int c3 = col0 + wn * 32 + nt * 8 + qd * 2;
            int cc = c3 & 1023;
            int hh = cc >> 6;
            int d = cc & 63;
            float mul = (which == 0) ? QSCALE : 1.0f;
            float* a4 = acc[mt][nt];
            float v0 = a4[0] * mul, v1 = a4[1] * mul;
            float v2 = a4[2] * mul, v3 = a4[3] * mul;
            size_t head = ((size_t)b0 * HN + hh) * (size_t)NSEQ * DH;
            if (which == 0) {
                size_t idx = head + (size_t)n0 * DH + d;
                *(uint32_t*)(g_qhi + idx) =
                    h2u(__float2half_rn(v0), __float2half_rn(v1));
                *(uint32_t*)(g_qhi + idx + 8 * DH) =
                    h2u(__float2half_rn(v2), __float2half_rn(v3));
            } else if (which == 1) {
                __half h0, h1, h2, h3, l0, l1, l2, l3;
                splitf(v0, h0, l0); splitf(v1, h1, l1);
                splitf(v2, h2, l2); splitf(v3, h3, l3);
                size_t idx = head + (size_t)n0 * DH + d;
                *(uint32_t*)(g_khi + idx) = h2u(h0, h1);
                *(uint32_t*)(g_klo + idx) = h2u(l0, l1);
                *(uint32_t*)(g_khi + idx + 8 * DH) = h2u(h2, h3);
                *(uint32_t*)(g_klo + idx + 8 * DH) = h2u(l2, l3);
            } else {
                size_t idx = head + (size_t)d * NSEQ + n0;
                g_vhi[idx] = __float2half_rn(v0);
                g_vhi[idx + NSEQ] = __float2half_rn(v1);
                g_vhi[idx + 8] = __float2half_rn(v2);
                g_vhi[idx + NSEQ + 8] = __float2half_rn(v3);
            }
        }
    }
}

// ---------------------------------------------------------------------------
// Output projection GEMM (2-pass): avhi @ (wphi + wplo)
// ---------------------------------------------------------------------------
__global__ void __launch_bounds__(512, 1)
tc_gemm_proj(float* __restrict__ Cout)
{
    extern __shared__ __half smg[];
    const uint32_t sbase = smem_u32(smg);
    const int tid = threadIdx.x;
    const int wid = tid >> 5, lane = tid & 31;
    const int grp = lane >> 2, qd = lane & 3;
    const int wm = wid >> 2, wn = wid & 3;
    const int row0 = blockIdx.y * 128, col0 = blockIdx.x * 128;

    auto stage_load = [&](int s, int kb) {
        uint32_t so = sbase + (uint32_t)(s * G2_STAGE_B);
#pragma unroll
        for (int it = 0; it < 2; it++) {
            int f = tid + 512 * it;
            int row = f >> 3, q = f & 7;
            size_t asrc = (size_t)(row0 + row) * CDIM + kb * 64 + q * 8;
            cp16(so + (uint32_t)(row * GS + q * 8) * 2, g_avhi + asrc);
        }
#pragma unroll
        for (int it = 0; it < 2; it++) {
            int f = tid + 512 * it;
            int row = f >> 3, q = f & 7;
            size_t bsrc = (size_t)(col0 + row) * CDIM + kb * 64 + q * 8;
            uint32_t off = so + 18432 + (uint32_t)(row * GS + q * 8) * 2;
            cp16(off,         g_wphi + bsrc);
            cp16(off + 18432, g_wplo + bsrc);
        }
    };

    float acc[2][4][4];
#pragma unroll
    for (int i = 0; i < 2; i++)
#pragma unroll
        for (int j = 0; j < 4; j++)
#pragma unroll
            for (int t = 0; t < 4; t++) acc[i][j][t] = 0.f;

    stage_load(0, 0); CP_COMMIT();

    for (int kb = 0; kb < 16; kb++) {
        CP_WAIT(0);
        __syncthreads();
        if (kb < 15) { stage_load((kb + 1) & 1, kb + 1); CP_COMMIT(); }
        gemm_step2(sbase + (uint32_t)((kb & 1) * G2_STAGE_B), acc, wm, wn, lane);
    }

#pragma unroll
    for (int mt = 0; mt < 2; mt++) {
        int r = row0 + wm * 32 + mt * 16 + grp;
#pragma unroll
        for (int nt = 0; nt < 4; nt++) {
            int cl = col0 + wn * 32 + nt * 8 + qd * 2;
            float* a4 = acc[mt][nt];
            float2 v0 = {a4[0], a4[1]};
            float2 v1 = {a4[2], a4[3]};
            *(float2*)(Cout + (size_t)r * CDIM + cl) = v0;
            *(float2*)(Cout + (size_t)(r + 8) * CDIM + cl) = v1;
        }
    }
}

// ---------------------------------------------------------------------------
// Fused sigmoid attention: 128 q-rows per CTA, 64-key tiles, 2 CTAs/SM.
// S: 2-pass (qh·kh f32 + qh·kl f16).  PV: 1-pass (p·vh f32).
// smem (halfs): Qhi 0..9216 | K stage s @9216+s*9216 (hi 4608 + lo 4608)
//               | V stage s @27648+s*4608 (hi only). Total 36864 halfs.
// ---------------------------------------------------------------------------
#define AK_BASE 9216
#define AV_BASE 27648
#define ATTN_SMEM (36864 * 2)    // 73728 B

__global__ void __launch_bounds__(256, 2)
attn_kernel2(float* __restrict__ attn_out, float* __restrict__ av_out)
{
    extern __shared__ __half sma[];
    const uint32_t sbase = smem_u32(sma);
    const int tid = threadIdx.x;
    const int wid = tid >> 5, lane = tid & 31;
    const int grp = lane >> 2, qd = lane & 3;
    const int row0 = blockIdx.x * 128;
    const int bhid = blockIdx.y;
    const int b = bhid >> 4, h = bhid & 15;
    const size_t head = ((size_t)b * HN + h) * (size_t)NSEQ * DH;

    auto load_kv = [&](int jt_, int s) {
        uint32_t ko = sbase + (uint32_t)(AK_BASE + s * 9216) * 2;
        uint32_t vo = sbase + (uint32_t)(AV_BASE + s * 4608) * 2;
#pragma unroll
        for (int it = 0; it < 2; it++) {
            int f = tid + 256 * it;
            int row = f >> 3, q = f & 7;
            {
                size_t src = head + (size_t)(jt_ * 64 + row) * DH + q * 8;
                uint32_t off = ko + (uint32_t)(row * GS + q * 8) * 2;
                cp16(off,            g_khi + src);
                cp16(off + 4608 * 2, g_klo + src);
            }
            {
                size_t src = head + (size_t)row * NSEQ + (size_t)jt_ * 64 + q * 8;
                cp16(vo + (uint32_t)(row * GS + q * 8) * 2, g_vhi + src);
            }
        }
    };

    // prologue: Q (128x64, hi only) + tile 0
#pragma unroll
    for (int it = 0; it < 4; it++) {
        int f = tid + 256 * it;
        int row = f >> 3, q = f & 7;
        size_t src = head + (size_t)(row0 + row) * DH + q * 8;
        cp16(sbase + (uint32_t)(row * GS + q * 8) * 2, g_qhi + src);
    }
    load_kv(0, 0);
    CP_COMMIT();

    float oacc[8][4];
#pragma unroll
    for (int i = 0; i < 8; i++)
#pragma unroll
        for (int t = 0; t < 4; t++) oacc[i][t] = 0.f;

    for (int jt = 0; jt < NSEQ / 64; jt++) {
        CP_WAIT(0);
        __syncthreads();
        if (jt < NSEQ / 64 - 1) { load_kv(jt + 1, (jt + 1) & 1); CP_COMMIT(); }

        const uint32_t kb = sbase + (uint32_t)(AK_BASE + (jt & 1) * 9216) * 2;
        const uint32_t vb = sbase + (uint32_t)(AV_BASE + (jt & 1) * 4608) * 2;

        // ---- S = Q K^T (2-pass) ----
        float sacc[8][4];
        uint32_t sch[8][2];
#pragma unroll
        for (int i = 0; i < 8; i++) {
#pragma unroll
            for (int t = 0; t < 4; t++) sacc[i][t] = 0.f;
            sch[i][0] = 0u; sch[i][1] = 0u;
        }

#pragma unroll
        for (int ks = 0; ks < 4; ks++) {
            const int k0 = ks * 16;
            uint32_t qfh[4];
            ldsm_x4(qfh, a_addr(sbase, wid * 16, k0, SBY, lane));
#pragma unroll
            for (int t = 0; t < 4; t++) {
                uint32_t kh4[4], kl4[4];
                uint32_t kaddr = b_addr(kb, t * 16, k0, SBY, lane);
                ldsm_x4(kh4, kaddr);
                ldsm_x4(kl4, kaddr + 9216);
                mma_f32acc(sacc[2 * t],     qfh, kh4 + 0);
                mma_f32acc(sacc[2 * t + 1], qfh, kh4 + 2);
                mma_f16acc(sch[2 * t],      qfh, kl4 + 0);
                mma_f16acc(sch[2 * t + 1],  qfh, kl4 + 2);
            }
        }
#pragma unroll
        for (int i = 0; i < 8; i++) addcross(sacc[i], sch[i]);

        // ---- sigmoid + attn store + P (plain fp16) -> PV (1-pass) ----
        float* ab = attn_out
            ? attn_out + ((size_t)bhid * NSEQ + row0 + wid * 16 + grp) * NSEQ
                       + (size_t)jt * 64
            : nullptr;

#pragma unroll
        for (int kc = 0; kc < 4; kc++) {
            float* c0 = sacc[2 * kc];
            float* c1 = sacc[2 * kc + 1];
            float p0 = __fdividef(1.f, 1.f + __expf(-(c0[0] + ATTN_BIAS_F)));
            float p1 = __fdividef(1.f, 1.f + __expf(-(c0[1] + ATTN_BIAS_F)));
            float p2 = __fdividef(1.f, 1.f + __expf(-(c0[2] + ATTN_BIAS_F)));
            float p3 = __fdividef(1.f, 1.f + __expf(-(c0[3] + ATTN_BIAS_F)));
            float p4 = __fdividef(1.f, 1.f + __expf(-(c1[0] + ATTN_BIAS_F)));
            float p5 = __fdividef(1.f, 1.f + __expf(-(c1[1] + ATTN_BIAS_F)));
            float p6 = __fdividef(1.f, 1.f + __expf(-(c1[2] + ATTN_BIAS_F)));
            float p7 = __fdividef(1.f, 1.f + __expf(-(c1[3] + ATTN_BIAS_F)));
            if (ab) {
                float2 w0 = {p0, p1}, w1 = {p2, p3}, w2 = {p4, p5}, w3 = {p6, p7};
                *(float2*)(ab + kc * 16 + 2 * qd) = w0;
                *(float2*)(ab + 8 * NSEQ + kc * 16 + 2 * qd) = w1;
                *(float2*)(ab + kc * 16 + 8 + 2 * qd) = w2;
                *(float2*)(ab + 8 * NSEQ + kc * 16 + 8 + 2 * qd) = w3;
            }
            uint32_t pah[4] = {
                h2u(__float2half_rn(p0), __float2half_rn(p1)),
                h2u(__float2half_rn(p2), __float2half_rn(p3)),
                h2u(__float2half_rn(p4), __float2half_rn(p5)),
                h2u(__float2half_rn(p6), __float2half_rn(p7)) };
#pragma unroll
            for (int t = 0; t < 4; t++) {
                uint32_t vh4[4];
                ldsm_x4(vh4, b_addr(vb, t * 16, kc * 16, SBY, lane));
                mma_f32acc(oacc[2 * t],     pah, vh4 + 0);
                mma_f32acc(oacc[2 * t + 1], pah, vh4 + 2);
            }
        }
    }

    // ---- epilogue: O -> fp32 av_out + fp16 g_avhi ----
    const int r = row0 + wid * 16 + grp;
#pragma unroll
    for (int dt = 0; dt < 8; dt++) {
        int d = dt * 8 + qd * 2;
        size_t base = (((size_t)b * NSEQ + r) * HN + h) * DH + d;
        float2 v0 = {oacc[dt][0], oacc[dt][1]};
        float2 v1 = {oacc[dt][2], oacc[dt][3]};
        *(float2*)(av_out + base) = v0;
        *(float2*)(av_out + base + 8 * (size_t)CDIM) = v1;
        *(uint32_t*)(g_avhi + base) =
            h2u(__float2half_rn(v0.x), __float2half_rn(v0.y));
        *(uint32_t*)(g_avhi + base + 8 * (size_t)CDIM) =
            h2u(__float2half_rn(v1.x), __float2half_rn(v1.y));
    }
}

// ---------------------------------------------------------------------------
// Launch
// ---------------------------------------------------------------------------
extern "C" void kernel_launch(void* const* d_in, const int* in_sizes, int n_in,
                              void* d_out, int out_size)
{
    const float* x     = (const float*)d_in[0];
    const float* wqkv  = (const float*)d_in[1];
    const float* wproj = (const float*)d_in[2];
    float* out = (float*)d_out;

    const size_t SZ_ATTN = (size_t)BSZ * HN * NSEQ * NSEQ;
    const size_t SZ_AV   = (size_t)BSZ * NSEQ * CDIM;
    const bool full = ((size_t)out_size >= SZ_ATTN + 2 * SZ_AV);

    static float* g_av_dev = nullptr;
    static bool attr_done = false;
    if (!attr_done) {
        cudaFuncSetAttribute(tc_gemm_qkv,
                             cudaFuncAttributeMaxDynamicSharedMemorySize, GEMM3_SMEM);
        cudaFuncSetAttribute(attn_kernel2,
                             cudaFuncAttributeMaxDynamicSharedMemorySize, ATTN_SMEM);
        cudaFuncSetAttribute(tc_gemm_proj,
                             cudaFuncAttributeMaxDynamicSharedMemorySize, GEMM2_SMEM);
        cudaGetSymbolAddress((void**)&g_av_dev, g_av);
        attr_done = true;
    }

    // 0) split-convert inputs
    convert_x<<<(int)(NELEM_X / 4 / 256), 256>>>(x);
    convert_w<<<(int)(NELEM_W / 4 / 256), 256>>>(wqkv);
    convert_wp<<<(int)(NELEM_WP / 4 / 256), 256>>>(wproj);

    // 1) QKV projection: K block 3-pass, Q/V blocks 2-pass
    tc_gemm_qkv<<<dim3(3 * CDIM / 128, (BSZ * NSEQ) / 128), 512, GEMM3_SMEM>>>();

    // 2) Fused sigmoid attention (S 2-pass, PV 1-pass)
    float* attn_dst = full ? out : nullptr;
    float* av_dst   = full ? out + SZ_ATTN : g_av_dev;
    attn_kernel2<<<dim3(NSEQ / 128, BSZ * HN), 256, ATTN_SMEM>>>(attn_dst, av_dst);

    // 3) Output projection (2-pass)
    float* proj_dst = full ? out + SZ_ATTN + SZ_AV : out;
    tc_gemm_proj<<<dim3(CDIM / 128, (BSZ * NSEQ) / 128), 512, GEMM2_SMEM>>>(proj_dst);
}

// round 17
// speedup vs baseline: 1.5429x; 1.0931x over previous
#include <cuda_runtime.h>
#include <cuda_fp16.h>
#include <cstdint>
#include <cstddef>

// Problem constants
#define BSZ   2
#define NSEQ  2048
#define CDIM  1024
#define HN    16
#define DH    64
#define QSCALE 0.125f
#define ATTN_BIAS_F (-7.625f)

#define NELEM_X   ((size_t)BSZ * NSEQ * CDIM)
#define NELEM_W   ((size_t)3 * CDIM * CDIM)
#define NELEM_WP  ((size_t)CDIM * CDIM)
#define NELEM_HD  ((size_t)BSZ * HN * NSEQ * DH)

__device__ __half g_xhi[NELEM_X];                     // x: plain fp16
__device__ __half g_whi[NELEM_W],  g_wlo[NELEM_W];    // wqkv: split
__device__ __half g_wphi[NELEM_WP], g_wplo[NELEM_WP]; // wproj: split
__device__ __half g_qhi[NELEM_HD];                    // q: plain fp16 (scaled)
__device__ __half g_khi[NELEM_HD];                    // k: plain fp16
__device__ __half g_vhi[NELEM_HD];                    // v^T: plain fp16
__device__ __half g_avhi[NELEM_X];                    // av: plain fp16
__device__ float g_av[NELEM_X];

// ---------------------------------------------------------------------------
// Helpers
// ---------------------------------------------------------------------------
__device__ __forceinline__ uint32_t smem_u32(const void* p) {
    uint32_t a;
    asm("{ .reg .u64 t; cvta.to.shared.u64 t, %1; cvt.u32.u64 %0, t; }"
        : "=r"(a) : "l"(p));
    return a;
}

__device__ __forceinline__ void mma_f32acc(float c[4], const uint32_t a[4],
                                           const uint32_t b[2]) {
    asm volatile(
        "mma.sync.aligned.m16n8k16.row.col.f32.f16.f16.f32 "
        "{%0,%1,%2,%3}, {%4,%5,%6,%7}, {%8,%9}, {%0,%1,%2,%3};\n"
        : "+f"(c[0]), "+f"(c[1]), "+f"(c[2]), "+f"(c[3])
        : "r"(a[0]), "r"(a[1]), "r"(a[2]), "r"(a[3]), "r"(b[0]), "r"(b[1]));
}
__device__ __forceinline__ void mma_f16acc(uint32_t c[2], const uint32_t a[4],
                                           const uint32_t b[2]) {
    asm volatile(
        "mma.sync.aligned.m16n8k16.row.col.f16.f16.f16.f16 "
        "{%0,%1}, {%2,%3,%4,%5}, {%6,%7}, {%0,%1};\n"
        : "+r"(c[0]), "+r"(c[1])
        : "r"(a[0]), "r"(a[1]), "r"(a[2]), "r"(a[3]), "r"(b[0]), "r"(b[1]));
}
__device__ __forceinline__ void addcross(float c[4], const uint32_t ch[2]) {
    float2 v0 = __half22float2(*(const __half2*)&ch[0]);
    float2 v1 = __half22float2(*(const __half2*)&ch[1]);
    c[0] += v0.x; c[1] += v0.y; c[2] += v1.x; c[3] += v1.y;
}

__device__ __forceinline__ void ldsm_x4(uint32_t r[4], uint32_t addr) {
    asm volatile("ldmatrix.sync.aligned.m8n8.x4.shared.b16 {%0,%1,%2,%3}, [%4];"
                 : "=r"(r[0]), "=r"(r[1]), "=r"(r[2]), "=r"(r[3]) : "r"(addr));
}
__device__ __forceinline__ uint32_t a_addr(uint32_t base, int row0, int k0,
                                           int SB, int lane) {
    int mat = lane >> 3, r = lane & 7;
    int row = row0 + r + ((mat & 1) << 3);
    int k   = k0 + ((mat >> 1) << 3);
    return base + row * SB + k * 2;
}
__device__ __forceinline__ uint32_t b_addr(uint32_t base, int n0, int k0,
                                           int SB, int lane) {
    int mat = lane >> 3, r = lane & 7;
    int row = n0 + r + ((mat >> 1) << 3);
    int k   = k0 + ((mat & 1) << 3);
    return base + row * SB + k * 2;
}

__device__ __forceinline__ void splitf(float v, __half& h, __half& l) {
    h = __float2half_rn(v);
    l = __float2half_rn(v - __half2float(h));
}
__device__ __forceinline__ uint32_t h2u(__half a, __half b) {
    __half2 t = __halves2half2(a, b);
    return *reinterpret_cast<uint32_t*>(&t);
}

__device__ __forceinline__ void cp16(uint32_t dst, const void* src) {
    asm volatile("cp.async.cg.shared.global [%0], [%1], 16;" :: "r"(dst), "l"(src));
}
#define CP_COMMIT() asm volatile("cp.async.commit_group;" ::: "memory")
#define CP_WAIT(N)  asm volatile("cp.async.wait_group %0;" :: "n"(N) : "memory")

// ---------------------------------------------------------------------------
// Elementwise converters
// ---------------------------------------------------------------------------
__global__ void convert_x(const float* __restrict__ src) {
    int i = blockIdx.x * blockDim.x + threadIdx.x;
    float4 v = ((const float4*)src)[i];
    uint2 hi;
    hi.x = h2u(__float2half_rn(v.x), __float2half_rn(v.y));
    hi.y = h2u(__float2half_rn(v.z), __float2half_rn(v.w));
    ((uint2*)g_xhi)[i] = hi;
}
__global__ void convert_w(const float* __restrict__ src) {
    int i = blockIdx.x * blockDim.x + threadIdx.x;
    float4 v = ((const float4*)src)[i];
    __half h0, h1, h2, h3, l0, l1, l2, l3;
    splitf(v.x, h0, l0); splitf(v.y, h1, l1);
    splitf(v.z, h2, l2); splitf(v.w, h3, l3);
    uint2 hi = { h2u(h0, h1), h2u(h2, h3) };
    uint2 lo = { h2u(l0, l1), h2u(l2, l3) };
    ((uint2*)g_whi)[i] = hi;
    ((uint2*)g_wlo)[i] = lo;
}
__global__ void convert_wp(const float* __restrict__ src) {
    int i = blockIdx.x * blockDim.x + threadIdx.x;
    float4 v = ((const float4*)src)[i];
    __half h0, h1, h2, h3, l0, l1, l2, l3;
    splitf(v.x, h0, l0); splitf(v.y, h1, l1);
    splitf(v.z, h2, l2); splitf(v.w, h3, l3);
    uint2 hi = { h2u(h0, h1), h2u(h2, h3) };
    uint2 lo = { h2u(l0, l1), h2u(l2, l3) };
    ((uint2*)g_wphi)[i] = hi;
    ((uint2*)g_wplo)[i] = lo;
}

// ---------------------------------------------------------------------------
// GEMM: 128x128 CTA tile, 512 threads, 16 warps (4x4, M32xN32/warp),
// K-chunk 64, cp.async double-buffered, ldmatrix loads, 2-pass:
// Ahi·(Bhi+Blo).  Stage (bytes): Ahi 0 | Bhi 18432 | Blo 36864; 55296/stage
// ---------------------------------------------------------------------------
#define GS 72
#define SBY (GS * 2)
#define G2_STAGE_B 55296
#define GEMM2_SMEM (2 * G2_STAGE_B)    // 110592 B

__device__ __forceinline__ void gemm_step2(
    uint32_t sA, float acc[2][4][4], int wm, int wn, int lane)
{
    uint32_t cch[2][4][2];
#pragma unroll
    for (int i = 0; i < 2; i++)
#pragma unroll
        for (int j = 0; j < 4; j++) { cch[i][j][0] = 0u; cch[i][j][1] = 0u; }

#pragma unroll
    for (int ks = 0; ks < 4; ks++) {
        const int k0 = ks * 16;
        uint32_t bh0[4], bh1[4], bl0[4], bl1[4];
        uint32_t ba0 = b_addr(sA + 18432, wn * 32,      k0, SBY, lane);
        uint32_t ba1 = b_addr(sA + 18432, wn * 32 + 16, k0, SBY, lane);
        ldsm_x4(bh0, ba0);
        ldsm_x4(bh1, ba1);
        ldsm_x4(bl0, ba0 + 18432);
        ldsm_x4(bl1, ba1 + 18432);
#pragma unroll
        for (int mt = 0; mt < 2; mt++) {
            uint32_t ah[4];
            ldsm_x4(ah, a_addr(sA, wm * 32 + mt * 16, k0, SBY, lane));
            mma_f32acc(acc[mt][0], ah, bh0 + 0);
            mma_f32acc(acc[mt][1], ah, bh0 + 2);
            mma_f32acc(acc[mt][2], ah, bh1 + 0);
            mma_f32acc(acc[mt][3], ah, bh1 + 2);
            mma_f16acc(cch[mt][0], ah, bl0 + 0);
            mma_f16acc(cch[mt][1], ah, bl0 + 2);
            mma_f16acc(cch[mt][2], ah, bl1 + 0);
            mma_f16acc(cch[mt][3], ah, bl1 + 2);
        }
    }
#pragma unroll
    for (int i = 0; i < 2; i++)
#pragma unroll
        for (int j = 0; j < 4; j++) addcross(acc[i][j], cch[i][j]);
}

// ---------------------------------------------------------------------------
// QKV GEMM (2-pass everywhere): xh @ (wh + wl)^T
// ---------------------------------------------------------------------------
__global__ void __launch_bounds__(512, 1)
tc_gemm_qkv()
{
    extern __shared__ __half smg[];
    const uint32_t sbase = smem_u32(smg);
    const int tid = threadIdx.x;
    const int wid = tid >> 5, lane = tid & 31;
    const int grp = lane >> 2, qd = lane & 3;
    const int wm = wid >> 2, wn = wid & 3;
    const int row0 = blockIdx.y * 128, col0 = blockIdx.x * 128;
    const int which = col0 >> 10;          // 0=q, 1=k, 2=v (uniform per CTA)

    auto stage_load = [&](int s, int kb) {
        uint32_t so = sbase + (uint32_t)(s * G2_STAGE_B);
        {   // A: 128 rows x 64 halves (hi only) = 512 cp16
            int row = tid >> 2, q = tid & 3;
            size_t asrc = (size_t)(row0 + row) * CDIM + kb * 64 + q * 16;
            uint32_t off = so + (uint32_t)(row * GS + q * 16) * 2;
            cp16(off,      g_xhi + asrc);
            cp16(off + 16, g_xhi + asrc + 8);
        }
#pragma unroll
        for (int it = 0; it < 2; it++) {     // B: hi + lo
            int f = tid + 512 * it;
            int row = f >> 3, q = f & 7;
            size_t bsrc = (size_t)(col0 + row) * CDIM + kb * 64 + q * 8;
            uint32_t off = so + 18432 + (uint32_t)(row * GS + q * 8) * 2;
            cp16(off,         g_whi + bsrc);
            cp16(off + 18432, g_wlo + bsrc);
        }
    };

    float acc[2][4][4];
#pragma unroll
    for (int i = 0; i < 2; i++)
#pragma unroll
        for (int j = 0; j < 4; j++)
#pragma unroll
            for (int t = 0; t < 4; t++) acc[i][j][t] = 0.f;

    stage_load(0, 0); CP_COMMIT();

    for (int kb = 0; kb < 16; kb++) {
        CP_WAIT(0);
        __syncthreads();
        if (kb < 15) { stage_load((kb + 1) & 1, kb + 1); CP_COMMIT(); }
        gemm_step2(sbase + (uint32_t)((kb & 1) * G2_STAGE_B), acc, wm, wn, lane);
    }

    // epilogue: q/k plain fp16 row-major (q scaled), v plain fp16 transposed
#pragma unroll
    for (int mt = 0; mt < 2; mt++) {
        int r = row0 + wm * 32 + mt * 16 + grp;
        int b0 = r >> 11, n0 = r & 2047;
#pragma unroll
        for (int nt = 0; nt < 4; nt++) {
            int c3 = col0 + wn * 32 + nt * 8 + qd * 2;
            int cc = c3 & 1023;
            int hh = cc >> 6;
            int d = cc & 63;
            float mul = (which == 0) ? QSCALE : 1.0f;
            float* a4 = acc[mt][nt];
            float v0 = a4[0] * mul, v1 = a4[1] * mul;
            float v2 = a4[2] * mul, v3 = a4[3] * mul;
            size_t head = ((size_t)b0 * HN + hh) * (size_t)NSEQ * DH;
            if (which < 2) {
                __half* dst = which ? g_khi : g_qhi;
                size_t idx = head + (size_t)n0 * DH + d;
                *(uint32_t*)(dst + idx) =
                    h2u(__float2half_rn(v0), __float2half_rn(v1));
                *(uint32_t*)(dst + idx + 8 * DH) =
                    h2u(__float2half_rn(v2), __float2half_rn(v3));
            } else {
                size_t idx = head + (size_t)d * NSEQ + n0;
                g_vhi[idx] = __float2half_rn(v0);
                g_vhi[idx + NSEQ] = __float2half_rn(v1);
                g_vhi[idx + 8] = __float2half_rn(v2);
                g_vhi[idx + NSEQ + 8] = __float2half_rn(v3);
            }
        }
    }
}

// ---------------------------------------------------------------------------
// Output projection GEMM (2-pass): avhi @ (wphi + wplo)
// ---------------------------------------------------------------------------
__global__ void __launch_bounds__(512, 1)
tc_gemm_proj(float* __restrict__ Cout)
{
    extern __shared__ __half smg[];
    const uint32_t sbase = smem_u32(smg);
    const int tid = threadIdx.x;
    const int wid = tid >> 5, lane = tid & 31;
    const int grp = lane >> 2, qd = lane & 3;
    const int wm = wid >> 2, wn = wid & 3;
    const int row0 = blockIdx.y * 128, col0 = blockIdx.x * 128;

    auto stage_load = [&](int s, int kb) {
        uint32_t so = sbase + (uint32_t)(s * G2_STAGE_B);
        {
            int row = tid >> 2, q = tid & 3;
            size_t asrc = (size_t)(row0 + row) * CDIM + kb * 64 + q * 16;
            uint32_t off = so + (uint32_t)(row * GS + q * 16) * 2;
            cp16(off,      g_avhi + asrc);
            cp16(off + 16, g_avhi + asrc + 8);
        }
#pragma unroll
        for (int it = 0; it < 2; it++) {
            int f = tid + 512 * it;
            int row = f >> 3, q = f & 7;
            size_t bsrc = (size_t)(col0 + row) * CDIM + kb * 64 + q * 8;
            uint32_t off = so + 18432 + (uint32_t)(row * GS + q * 8) * 2;
            cp16(off,         g_wphi + bsrc);
            cp16(off + 18432, g_wplo + bsrc);
        }
    };

    float acc[2][4][4];
#pragma unroll
    for (int i = 0; i < 2; i++)
#pragma unroll
        for (int j = 0; j < 4; j++)
#pragma unroll
            for (int t = 0; t < 4; t++) acc[i][j][t] = 0.f;

    stage_load(0, 0); CP_COMMIT();

    for (int kb = 0; kb < 16; kb++) {
        CP_WAIT(0);
        __syncthreads();
        if (kb < 15) { stage_load((kb + 1) & 1, kb + 1); CP_COMMIT(); }
        gemm_step2(sbase + (uint32_t)((kb & 1) * G2_STAGE_B), acc, wm, wn, lane);
    }

#pragma unroll
    for (int mt = 0; mt < 2; mt++) {
        int r = row0 + wm * 32 + mt * 16 + grp;
#pragma unroll
        for (int nt = 0; nt < 4; nt++) {
            int cl = col0 + wn * 32 + nt * 8 + qd * 2;
            float* a4 = acc[mt][nt];
            float2 v0 = {a4[0], a4[1]};
            float2 v1 = {a4[2], a4[3]};
            *(float2*)(Cout + (size_t)r * CDIM + cl) = v0;
            *(float2*)(Cout + (size_t)(r + 8) * CDIM + cl) = v1;
        }
    }
}

// ---------------------------------------------------------------------------
// Fused sigmoid attention: 128 q-rows per CTA, 64-key tiles, 2 CTAs/SM.
// S: 1-pass (qh·kh f32).  PV: 1-pass (p·vh f32).
// smem (halfs): Qhi 0..9216 | K stage s @9216+s*4608 | V stage s @18432+s*4608
// Total 27648 halfs = 55296 B.
// ---------------------------------------------------------------------------
#define AK_BASE 9216
#define AV_BASE 18432
#define ATTN_SMEM (27648 * 2)    // 55296 B

__global__ void __launch_bounds__(256, 2)
attn_kernel2(float* __restrict__ attn_out, float* __restrict__ av_out)
{
    extern __shared__ __half sma[];
    const uint32_t sbase = smem_u32(sma);
    const int tid = threadIdx.x;
    const int wid = tid >> 5, lane = tid & 31;
    const int grp = lane >> 2, qd = lane & 3;
    const int row0 = blockIdx.x * 128;
    const int bhid = blockIdx.y;
    const int b = bhid >> 4, h = bhid & 15;
    const size_t head = ((size_t)b * HN + h) * (size_t)NSEQ * DH;

    auto load_kv = [&](int jt_, int s) {
        uint32_t ko = sbase + (uint32_t)(AK_BASE + s * 4608) * 2;
        uint32_t vo = sbase + (uint32_t)(AV_BASE + s * 4608) * 2;
#pragma unroll
        for (int it = 0; it < 2; it++) {
            int f = tid + 256 * it;
            int row = f >> 3, q = f & 7;
            {   // K tile: [64 keys][64 d] hi only
                size_t src = head + (size_t)(jt_ * 64 + row) * DH + q * 8;
                cp16(ko + (uint32_t)(row * GS + q * 8) * 2, g_khi + src);
            }
            {   // V^T tile: [64 d][64 keys] hi only
                size_t src = head + (size_t)row * NSEQ + (size_t)jt_ * 64 + q * 8;
                cp16(vo + (uint32_t)(row * GS + q * 8) * 2, g_vhi + src);
            }
        }
    };

    // prologue: Q (128x64, hi only) + tile 0
#pragma unroll
    for (int it = 0; it < 4; it++) {
        int f = tid + 256 * it;
        int row = f >> 3, q = f & 7;
        size_t src = head + (size_t)(row0 + row) * DH + q * 8;
        cp16(sbase + (uint32_t)(row * GS + q * 8) * 2, g_qhi + src);
    }
    load_kv(0, 0);
    CP_COMMIT();

    float oacc[8][4];
#pragma unroll
    for (int i = 0; i < 8; i++)
#pragma unroll
        for (int t = 0; t < 4; t++) oacc[i][t] = 0.f;

    for (int jt = 0; jt < NSEQ / 64; jt++) {
        CP_WAIT(0);
        __syncthreads();
        if (jt < NSEQ / 64 - 1) { load_kv(jt + 1, (jt + 1) & 1); CP_COMMIT(); }

        const uint32_t kb = sbase + (uint32_t)(AK_BASE + (jt & 1) * 4608) * 2;
        const uint32_t vb = sbase + (uint32_t)(AV_BASE + (jt & 1) * 4608) * 2;

        // ---- S = Q K^T (1-pass) ----
        float sacc[8][4];
#pragma unroll
        for (int i = 0; i < 8; i++)
#pragma unroll
            for (int t = 0; t < 4; t++) sacc[i][t] = 0.f;

#pragma unroll
        for (int ks = 0; ks < 4; ks++) {
            const int k0 = ks * 16;
            uint32_t qfh[4];
            ldsm_x4(qfh, a_addr(sbase, wid * 16, k0, SBY, lane));
#pragma unroll
            for (int t = 0; t < 4; t++) {
                uint32_t kh4[4];
                ldsm_x4(kh4, b_addr(kb, t * 16, k0, SBY, lane));
                mma_f32acc(sacc[2 * t],     qfh, kh4 + 0);
                mma_f32acc(sacc[2 * t + 1], qfh, kh4 + 2);
            }
        }

        // ---- sigmoid + attn store + P (plain fp16) -> PV (1-pass) ----
        float* ab = attn_out
            ? attn_out + ((size_t)bhid * NSEQ + row0 + wid * 16 + grp) * NSEQ
                       + (size_t)jt * 64
            : nullptr;

#pragma unroll
        for (int kc = 0; kc < 4; kc++) {
            float* c0 = sacc[2 * kc];
            float* c1 = sacc[2 * kc + 1];
            float p0 = __fdividef(1.f, 1.f + __expf(-(c0[0] + ATTN_BIAS_F)));
            float p1 = __fdividef(1.f, 1.f + __expf(-(c0[1] + ATTN_BIAS_F)));
            float p2 = __fdividef(1.f, 1.f + __expf(-(c0[2] + ATTN_BIAS_F)));
            float p3 = __fdividef(1.f, 1.f + __expf(-(c0[3] + ATTN_BIAS_F)));
            float p4 = __fdividef(1.f, 1.f + __expf(-(c1[0] + ATTN_BIAS_F)));
            float p5 = __fdividef(1.f, 1.f + __expf(-(c1[1] + ATTN_BIAS_F)));
            float p6 = __fdividef(1.f, 1.f + __expf(-(c1[2] + ATTN_BIAS_F)));
            float p7 = __fdividef(1.f, 1.f + __expf(-(c1[3] + ATTN_BIAS_F)));
            if (ab) {
                float2 w0 = {p0, p1}, w1 = {p2, p3}, w2 = {p4, p5}, w3 = {p6, p7};
                *(float2*)(ab + kc * 16 + 2 * qd) = w0;
                *(float2*)(ab + 8 * NSEQ + kc * 16 + 2 * qd) = w1;
                *(float2*)(ab + kc * 16 + 8 + 2 * qd) = w2;
                *(float2*)(ab + 8 * NSEQ + kc * 16 + 8 + 2 * qd) = w3;
            }
            uint32_t pah[4] = {
                h2u(__float2half_rn(p0), __float2half_rn(p1)),
                h2u(__float2half_rn(p2), __float2half_rn(p3)),
                h2u(__float2half_rn(p4), __float2half_rn(p5)),
                h2u(__float2half_rn(p6), __float2half_rn(p7)) };
#pragma unroll
            for (int t = 0; t < 4; t++) {
                uint32_t vh4[4];
                ldsm_x4(vh4, b_addr(vb, t * 16, kc * 16, SBY, lane));
                mma_f32acc(oacc[2 * t],     pah, vh4 + 0);
                mma_f32acc(oacc[2 * t + 1], pah, vh4 + 2);
            }
        }
    }

    // ---- epilogue: O -> fp32 av_out + fp16 g_avhi ----
    const int r = row0 + wid * 16 + grp;
#pragma unroll
    for (int dt = 0; dt < 8; dt++) {
        int d = dt * 8 + qd * 2;
        size_t base = (((size_t)b * NSEQ + r) * HN + h) * DH + d;
        float2 v0 = {oacc[dt][0], oacc[dt][1]};
        float2 v1 = {oacc[dt][2], oacc[dt][3]};
        *(float2*)(av_out + base) = v0;
        *(float2*)(av_out + base + 8 * (size_t)CDIM) = v1;
        *(uint32_t*)(g_avhi + base) =
            h2u(__float2half_rn(v0.x), __float2half_rn(v0.y));
        *(uint32_t*)(g_avhi + base + 8 * (size_t)CDIM) =
            h2u(__float2half_rn(v1.x), __float2half_rn(v1.y));
    }
}

// ---------------------------------------------------------------------------
// Launch
// ---------------------------------------------------------------------------
extern "C" void kernel_launch(void* const* d_in, const int* in_sizes, int n_in,
                              void* d_out, int out_size)
{
    const float* x     = (const float*)d_in[0];
    const float* wqkv  = (const float*)d_in[1];
    const float* wproj = (const float*)d_in[2];
    float* out = (float*)d_out;

    const size_t SZ_ATTN = (size_t)BSZ * HN * NSEQ * NSEQ;
    const size_t SZ_AV   = (size_t)BSZ * NSEQ * CDIM;
    const bool full = ((size_t)out_size >= SZ_ATTN + 2 * SZ_AV);

    static float* g_av_dev = nullptr;
    static bool attr_done = false;
    if (!attr_done) {
        cudaFuncSetAttribute(tc_gemm_qkv,
                             cudaFuncAttributeMaxDynamicSharedMemorySize, GEMM2_SMEM);
        cudaFuncSetAttribute(attn_kernel2,
                             cudaFuncAttributeMaxDynamicSharedMemorySize, ATTN_SMEM);
        cudaFuncSetAttribute(tc_gemm_proj,
                             cudaFuncAttributeMaxDynamicSharedMemorySize, GEMM2_SMEM);
        cudaGetSymbolAddress((void**)&g_av_dev, g_av);
        attr_done = true;
    }

    // 0) convert inputs (x plain fp16; weights split)
    convert_x<<<(int)(NELEM_X / 4 / 256), 256>>>(x);
    convert_w<<<(int)(NELEM_W / 4 / 256), 256>>>(wqkv);
    convert_wp<<<(int)(NELEM_WP / 4 / 256), 256>>>(wproj);

    // 1) QKV projection (2-pass): q/k plain fp16, v^T plain fp16
    tc_gemm_qkv<<<dim3(3 * CDIM / 128, (BSZ * NSEQ) / 128), 512, GEMM2_SMEM>>>();

    // 2) Fused sigmoid attention (S 1-pass, PV 1-pass)
    float* attn_dst = full ? out : nullptr;
    float* av_dst   = full ? out + SZ_ATTN : g_av_dev;
    attn_kernel2<<<dim3(NSEQ / 128, BSZ * HN), 256, ATTN_SMEM>>>(attn_dst, av_dst);

    // 3) Output projection (2-pass)
    float* proj_dst = full ? out + SZ_ATTN + SZ_AV : out;
    tc_gemm_proj<<<dim3(CDIM / 128, (BSZ * NSEQ) / 128), 512, GEMM2_SMEM>>>(proj_dst);
}